// round 11
// baseline (speedup 1.0000x reference)
#include <cuda_runtime.h>
#include <cuda_bf16.h>
#include <cstdint>

typedef __nv_bfloat16 bf16;

#define BATCH 32768
#define NIMG  5
#define DIM   512
#define DCAT  600
#define M5    (BATCH * NIMG)
#define TS    (BATCH * 200)

// ---- fp32 scratch ----
__device__ __align__(128) float g_tmp[4 * TS];
__device__ __align__(128) float g_c[BATCH * DCAT];
__device__ __align__(128) float g_h[BATCH * DCAT];
__device__ __align__(128) float g_ci[BATCH * DIM];
__device__ __align__(128) float g_u[BATCH * DIM];
__device__ __align__(128) float g_score[M5];

// ---- bf16 split planes (x = p0 + p1 + p2, exact 24-bit decomposition) ----
#define FPS  ((long long)BATCH * 2560)
#define CPS  ((long long)BATCH * 640)
#define CIPS ((long long)BATCH * 512)
__device__ __align__(128) bf16 g_fa [3 * FPS];
__device__ __align__(128) bf16 g_ca [3 * CPS];
__device__ __align__(128) bf16 g_ha [3 * CPS];
__device__ __align__(128) bf16 g_cia[3 * CIPS];
__device__ __align__(128) bf16 g_w2a[3 * 200 * 1024];
__device__ __align__(128) bf16 g_w3a[3 * 200 * 1536];
__device__ __align__(128) bf16 g_w5a[3 * 200 * 2560];
__device__ __align__(128) bf16 g_f1a[3 * 600 * 640];
__device__ __align__(128) bf16 g_f2a[3 * 512 * 640];
__device__ __align__(128) bf16 g_f0aa[3 * 512 * 512];
__device__ __align__(128) bf16 g_f0ua[3 * 512 * 512];

// ---- portable PTX helpers (sm_80+ ISA only; no 'a' features) ----
__device__ __forceinline__ uint32_t smem_u32(const void* p) {
    uint32_t a;
    asm("{ .reg .u64 t; cvta.to.shared.u64 t, %1; cvt.u32.u64 %0, t; }"
        : "=r"(a) : "l"(p));
    return a;
}
__device__ __forceinline__ void cp16(uint32_t saddr, const void* gaddr, uint32_t srcsz) {
    asm volatile("cp.async.cg.shared.global [%0], [%1], 16, %2;"
                 :: "r"(saddr), "l"(gaddr), "r"(srcsz));
}
__device__ __forceinline__ void ldm4(uint32_t& r0, uint32_t& r1, uint32_t& r2,
                                     uint32_t& r3, uint32_t addr) {
    asm volatile("ldmatrix.sync.aligned.m8n8.x4.shared.b16 {%0,%1,%2,%3}, [%4];"
                 : "=r"(r0), "=r"(r1), "=r"(r2), "=r"(r3) : "r"(addr));
}
__device__ __forceinline__ void mma16816(float* d, const uint32_t* a,
                                         const uint32_t* b) {
    asm volatile(
        "mma.sync.aligned.m16n8k16.row.col.f32.bf16.bf16.f32 "
        "{%0,%1,%2,%3}, {%4,%5,%6,%7}, {%8,%9}, {%0,%1,%2,%3};"
        : "+f"(d[0]), "+f"(d[1]), "+f"(d[2]), "+f"(d[3])
        : "r"(a[0]), "r"(a[1]), "r"(a[2]), "r"(a[3]), "r"(b[0]), "r"(b[1]));
}

// smem geometry: per buffer 3 A planes + 3 B planes, rows padded to 24 bf16 (48B)
#define PLANEB 6144          // 128 rows * 48 B
#define BUFB   (3 * PLANEB)  // 18432 B
#define SMT    (4 * BUFB)    // A[2 bufs] + B[2 bufs] = 73728 B

// ---------------------------------------------------------------------------
// Tensor-core GEMM via bf16x3 split, SPLIT ACCUMULATORS:
//   accM <- p0(A)*p0(B)            (same rounding profile as fp32 GEMM)
//   accC <- p0p1+p1p0+p1p1+p0p2+p2p0  (all O(2^-9): self-rounding negligible)
//   C = accM + accC  (single merge add in epilogue)
//   MODE 0:+bias  1:+bias,relu  2:raw (+z offset on C)  3: fused score epilogue
// Requires: M%128==0, K%16==0.
// ---------------------------------------------------------------------------
template<int MODE>
__global__ void __launch_bounds__(256, 1) tgemm(
    const bf16* __restrict__ A, long long aPS, int lda, long long aZ,
    const bf16* __restrict__ B, long long bPS, int ldb,
    const float* __restrict__ bias,
    float* __restrict__ C, int ldc, long long cZ,
    int Nn, int K,
    const float* __restrict__ u, const float* __restrict__ sw)
{
    extern __shared__ char smem[];
    const uint32_t sb  = smem_u32(smem);
    const uint32_t sbB = sb + 2 * BUFB;
    const int tid  = threadIdx.x;
    const int lane = tid & 31, wid = tid >> 5;
    const int wm = wid >> 2, wn = wid & 3;          // 2 x 4 warp grid
    const int bm = blockIdx.x * 128, bn = blockIdx.y * 128;

    A += (long long)blockIdx.z * aZ;
    if (MODE == 2) C += (long long)blockIdx.z * cZ;

    float accM[4][4][4], accC[4][4][4];
#pragma unroll
    for (int i = 0; i < 4; i++)
#pragma unroll
        for (int j = 0; j < 4; j++)
#pragma unroll
            for (int r = 0; r < 4; r++) { accM[i][j][r] = 0.f; accC[i][j][r] = 0.f; }

    // per-thread loader coords (256 threads fill one 128x16 plane per iter)
    const int lrow = (tid & 255) >> 1, lhalf = tid & 1;

    // ldmatrix lane-offset terms (within a plane)
    const uint32_t aOff = (uint32_t)((wm * 64 + (lane & 15)) * 48 + (lane >> 4) * 16);
    const uint32_t bOff = (uint32_t)((wn * 32 + (lane & 7) + ((lane >> 4) & 1) * 8) * 48
                                     + ((lane >> 3) & 1) * 16);

    const int nch = K >> 4;
    int buf = 0;

    // ---- chunk loader (cp.async, zero-fill for OOB B rows) ----
    auto load_chunk = [&](int s, int bi) {
#pragma unroll
        for (int p = 0; p < 3; p++) {
            const bf16* g = A + (long long)p * aPS +
                            (long long)(bm + lrow) * lda + s * 16 + lhalf * 8;
            cp16(sb + bi * BUFB + p * PLANEB + lrow * 48 + lhalf * 16, g, 16);
        }
#pragma unroll
        for (int p = 0; p < 3; p++) {
            int n = bn + lrow;
            bool ok = n < Nn;
            const bf16* g = B + (long long)p * bPS +
                            (long long)(ok ? n : 0) * ldb + s * 16 + lhalf * 8;
            cp16(sbB + bi * BUFB + p * PLANEB + lrow * 48 + lhalf * 16, g, ok ? 16u : 0u);
        }
        asm volatile("cp.async.commit_group;");
    };

    load_chunk(0, 0);
    for (int s = 0; s < nch; ++s) {
        const bool more = (s + 1) < nch;
        if (more) load_chunk(s + 1, buf ^ 1);
        if (more) asm volatile("cp.async.wait_group 1;");
        else      asm volatile("cp.async.wait_group 0;");
        __syncthreads();

        // ---- 6 plane products; q=0 -> accM, q>=1 -> accC ----
        const int pi[6] = {0, 0, 1, 1, 0, 2};
        const int pj[6] = {0, 1, 0, 1, 2, 0};
#pragma unroll
        for (int q = 0; q < 6; q++) {
            const uint32_t abase = sb  + buf * BUFB + pi[q] * PLANEB + aOff;
            const uint32_t bbase = sbB + buf * BUFB + pj[q] * PLANEB + bOff;
            uint32_t af[4][4], bfr[4][2];
#pragma unroll
            for (int i = 0; i < 4; i++)
                ldm4(af[i][0], af[i][1], af[i][2], af[i][3], abase + i * (16 * 48));
            ldm4(bfr[0][0], bfr[0][1], bfr[1][0], bfr[1][1], bbase);
            ldm4(bfr[2][0], bfr[2][1], bfr[3][0], bfr[3][1], bbase + 16 * 48);
#pragma unroll
            for (int i = 0; i < 4; i++)
#pragma unroll
                for (int j = 0; j < 4; j++)
                    mma16816(q == 0 ? accM[i][j] : accC[i][j], af[i], bfr[j]);
        }
        __syncthreads();
        buf ^= 1;
    }

    // ---- epilogue (merge accM + accC once) ----
    const int gr = lane >> 2, tig = lane & 3;
    if (MODE == 3) {
#pragma unroll
        for (int i = 0; i < 4; i++) {
            const int m1 = bm + wm * 64 + i * 16 + gr;
            const int m2 = m1 + 8;
            const float* u1 = u + (long long)(m1 / NIMG) * DIM;
            const float* u2 = u + (long long)(m2 / NIMG) * DIM;
            float s1 = 0.f, s2 = 0.f;
#pragma unroll
            for (int j = 0; j < 4; j++) {
                const int c = bn + wn * 32 + j * 8 + 2 * tig;
                float w0 = sw[c], w1 = sw[c + 1];
                float v;
                v = (accM[i][j][0] + accC[i][j][0]) + u1[c];     s1 += fmaxf(v, 0.f) * w0;
                v = (accM[i][j][1] + accC[i][j][1]) + u1[c + 1]; s1 += fmaxf(v, 0.f) * w1;
                v = (accM[i][j][2] + accC[i][j][2]) + u2[c];     s2 += fmaxf(v, 0.f) * w0;
                v = (accM[i][j][3] + accC[i][j][3]) + u2[c + 1]; s2 += fmaxf(v, 0.f) * w1;
            }
            s1 += __shfl_xor_sync(0xffffffffu, s1, 1);
            s1 += __shfl_xor_sync(0xffffffffu, s1, 2);
            s2 += __shfl_xor_sync(0xffffffffu, s2, 1);
            s2 += __shfl_xor_sync(0xffffffffu, s2, 2);
            if (tig == 0) {
                atomicAdd(&g_score[m1], s1);
                atomicAdd(&g_score[m2], s2);
            }
        }
    } else {
#pragma unroll
        for (int i = 0; i < 4; i++) {
            const int m1 = bm + wm * 64 + i * 16 + gr;
#pragma unroll
            for (int j = 0; j < 4; j++) {
                const int c = bn + wn * 32 + j * 8 + 2 * tig;
                if (c < Nn) {
                    float b0 = 0.f, b1 = 0.f;
                    if (MODE != 2) { b0 = bias[c]; b1 = bias[c + 1]; }
                    float v0 = (accM[i][j][0] + accC[i][j][0]) + b0;
                    float v1 = (accM[i][j][1] + accC[i][j][1]) + b1;
                    float v2 = (accM[i][j][2] + accC[i][j][2]) + b0;
                    float v3 = (accM[i][j][3] + accC[i][j][3]) + b1;
                    if (MODE == 1) {
                        v0 = fmaxf(v0, 0.f); v1 = fmaxf(v1, 0.f);
                        v2 = fmaxf(v2, 0.f); v3 = fmaxf(v3, 0.f);
                    }
                    *(float2*)&C[(long long)m1 * ldc + c]       = make_float2(v0, v1);
                    *(float2*)&C[(long long)(m1 + 8) * ldc + c] = make_float2(v2, v3);
                }
            }
        }
    }
}

// ---------------------------------------------------------------------------
__global__ void split3(const float* __restrict__ src, bf16* __restrict__ dst,
                       long long ps, long long total, int srcCols, int dstCols)
{
    long long idx = (long long)blockIdx.x * blockDim.x + threadIdx.x;
    if (idx >= total) return;
    float x;
    if (srcCols == dstCols) x = src[idx];
    else {
        long long r = idx / dstCols;
        int k = (int)(idx - r * dstCols);
        x = (k < srcCols) ? src[r * srcCols + k] : 0.f;
    }
    bf16 b0 = __float2bfloat16(x);
    float r1 = x - __bfloat162float(b0);
    bf16 b1 = __float2bfloat16(r1);
    bf16 b2 = __float2bfloat16(r1 - __bfloat162float(b1));
    dst[idx] = b0; dst[ps + idx] = b1; dst[2 * ps + idx] = b2;
}

__global__ void split3T(const float* __restrict__ src, bf16* __restrict__ dst,
                        long long ps, int N, int K, int Kpad)
{
    int idx = blockIdx.x * blockDim.x + threadIdx.x;
    if (idx >= N * Kpad) return;
    int n = idx / Kpad, k = idx % Kpad;
    float x = (k < K) ? src[(long long)k * N + n] : 0.f;
    bf16 b0 = __float2bfloat16(x);
    float r1 = x - __bfloat162float(b0);
    bf16 b1 = __float2bfloat16(r1);
    bf16 b2 = __float2bfloat16(r1 - __bfloat162float(b1));
    dst[idx] = b0; dst[ps + idx] = b1; dst[2 * ps + idx] = b2;
}

__global__ void conv_reduce(const float* __restrict__ bias, int T, int coff)
{
    int idx = blockIdx.x * blockDim.x + threadIdx.x;
    if (idx >= BATCH * 200) return;
    int c = idx % 200, n = idx / 200;
    float v = g_tmp[idx];
    for (int t = 1; t < T; t++) v = fmaxf(v, g_tmp[(size_t)t * TS + idx]);
    g_c[(size_t)n * DCAT + coff + c] = fmaxf(v + bias[c], 0.f);
}

__global__ void zero_score()
{
    int i = blockIdx.x * blockDim.x + threadIdx.x;
    if (i < M5) g_score[i] = 0.f;
}

__global__ void finalize_f32(const float* __restrict__ fcs_b, float* __restrict__ out)
{
    int n = blockIdx.x * blockDim.x + threadIdx.x;
    if (n >= BATCH) return;
    float fb = fcs_b[0];
    float s[5];
#pragma unroll
    for (int i = 0; i < 5; i++) s[i] = g_score[n * 5 + i] + fb;
#pragma unroll
    for (int i = 0; i < 5; i++) {
        int si = n * 5 + i;
        out[si] = s[i];
        int r = 0;
#pragma unroll
        for (int j = 0; j < 5; j++)
            r += (s[j] > s[i]) || ((s[j] == s[i]) && (j < i));
        out[M5 + si] = (float)r;
    }
}

extern "C" void kernel_launch(void* const* d_in, const int* in_sizes, int n_in,
                              void* d_out, int out_size)
{
    const float* feats = (const float*)d_in[0];
    const float* w2    = (const float*)d_in[1];
    const float* b2    = (const float*)d_in[2];
    const float* w3    = (const float*)d_in[3];
    const float* b3    = (const float*)d_in[4];
    const float* w5    = (const float*)d_in[5];
    const float* b5    = (const float*)d_in[6];
    const float* fc1_w = (const float*)d_in[7];
    const float* fc1_b = (const float*)d_in[8];
    const float* fc2_w = (const float*)d_in[9];
    const float* fc2_b = (const float*)d_in[10];
    const float* fc0_w = (const float*)d_in[11];
    const float* fc0_b = (const float*)d_in[12];
    const float* fcs_w = (const float*)d_in[13];
    const float* fcs_b = (const float*)d_in[14];

    float *pt, *pc, *ph, *pci, *pu;
    cudaGetSymbolAddress((void**)&pt,  g_tmp);
    cudaGetSymbolAddress((void**)&pc,  g_c);
    cudaGetSymbolAddress((void**)&ph,  g_h);
    cudaGetSymbolAddress((void**)&pci, g_ci);
    cudaGetSymbolAddress((void**)&pu,  g_u);
    bf16 *fa, *ca, *ha, *cia, *w2a, *w3a, *w5a, *f1a, *f2a, *f0aa, *f0ua;
    cudaGetSymbolAddress((void**)&fa,   g_fa);
    cudaGetSymbolAddress((void**)&ca,   g_ca);
    cudaGetSymbolAddress((void**)&ha,   g_ha);
    cudaGetSymbolAddress((void**)&cia,  g_cia);
    cudaGetSymbolAddress((void**)&w2a,  g_w2a);
    cudaGetSymbolAddress((void**)&w3a,  g_w3a);
    cudaGetSymbolAddress((void**)&w5a,  g_w5a);
    cudaGetSymbolAddress((void**)&f1a,  g_f1a);
    cudaGetSymbolAddress((void**)&f2a,  g_f2a);
    cudaGetSymbolAddress((void**)&f0aa, g_f0aa);
    cudaGetSymbolAddress((void**)&f0ua, g_f0ua);

    cudaFuncSetAttribute(tgemm<0>, cudaFuncAttributeMaxDynamicSharedMemorySize, SMT);
    cudaFuncSetAttribute(tgemm<1>, cudaFuncAttributeMaxDynamicSharedMemorySize, SMT);
    cudaFuncSetAttribute(tgemm<2>, cudaFuncAttributeMaxDynamicSharedMemorySize, SMT);
    cudaFuncSetAttribute(tgemm<3>, cudaFuncAttributeMaxDynamicSharedMemorySize, SMT);

    dim3 blk(256);
    const int MB = BATCH / 128;

    // ---- splits ----
    split3<<<(int)((83886080LL + 255) / 256), blk>>>(feats, fa, FPS, 83886080LL, 2560, 2560);
    split3<<<(204800 + 255) / 256, blk>>>(w2, w2a, 200 * 1024, 204800, 1024, 1024);
    split3<<<(307200 + 255) / 256, blk>>>(w3, w3a, 200 * 1536, 307200, 1536, 1536);
    split3<<<(512000 + 255) / 256, blk>>>(w5, w5a, 200 * 2560, 512000, 2560, 2560);
    split3T<<<(600 * 640 + 255) / 256, blk>>>(fc1_w, f1a, 600 * 640, 600, 600, 640);
    split3T<<<(512 * 640 + 255) / 256, blk>>>(fc2_w, f2a, 512 * 640, 512, 600, 640);
    split3T<<<(512 * 512 + 255) / 256, blk>>>(fc0_w, f0aa, 512 * 512, 512, 512, 512);
    split3T<<<(512 * 512 + 255) / 256, blk>>>(fc0_w + (size_t)DIM * DIM, f0ua,
                                              512 * 512, 512, 512, 512);

    // ---- conv blocks ----
    tgemm<2><<<dim3(MB, 2, 4), blk, SMT>>>(fa, FPS, 2560, 512,
        w2a, 200 * 1024, 1024, nullptr, pt, 200, TS, 200, 1024, nullptr, nullptr);
    conv_reduce<<<(BATCH * 200 + 255) / 256, blk>>>(b2, 4, 0);

    tgemm<2><<<dim3(MB, 2, 3), blk, SMT>>>(fa, FPS, 2560, 512,
        w3a, 200 * 1536, 1536, nullptr, pt, 200, TS, 200, 1536, nullptr, nullptr);
    conv_reduce<<<(BATCH * 200 + 255) / 256, blk>>>(b3, 3, 200);

    tgemm<1><<<dim3(MB, 2, 1), blk, SMT>>>(fa, FPS, 2560, 0,
        w5a, 200 * 2560, 2560, b5, pc + 400, DCAT, 0, 200, 2560, nullptr, nullptr);

    // ---- fc1 ----
    split3<<<(int)(((long long)BATCH * 640 + 255) / 256), blk>>>(pc, ca, CPS,
        (long long)BATCH * 640, 600, 640);
    tgemm<1><<<dim3(MB, 5, 1), blk, SMT>>>(ca, CPS, 640, 0,
        f1a, 600 * 640, 640, fc1_b, ph, DCAT, 0, 600, 640, nullptr, nullptr);

    // ---- fc2 ----
    split3<<<(int)(((long long)BATCH * 640 + 255) / 256), blk>>>(ph, ha, CPS,
        (long long)BATCH * 640, 600, 640);
    tgemm<0><<<dim3(MB, 4, 1), blk, SMT>>>(ha, CPS, 640, 0,
        f2a, 512 * 640, 640, fc2_b, pci, DIM, 0, 512, 640, nullptr, nullptr);

    // ---- u = ci @ fc0_w[512:] + fc0_b ----
    split3<<<(int)(((long long)BATCH * 512 + 255) / 256), blk>>>(pci, cia, CIPS,
        (long long)BATCH * 512, 512, 512);
    tgemm<0><<<dim3(MB, 4, 1), blk, SMT>>>(cia, CIPS, 512, 0,
        f0ua, 512 * 512, 512, fc0_b, pu, DIM, 0, 512, 512, nullptr, nullptr);

    // ---- fused score GEMM ----
    zero_score<<<(M5 + 255) / 256, blk>>>();
    tgemm<3><<<dim3(M5 / 128, 4, 1), blk, SMT>>>(fa, FPS, 512, 0,
        f0aa, 512 * 512, 512, nullptr, nullptr, 0, 0, 512, 512, pu, fcs_w);

    finalize_f32<<<(BATCH + 255) / 256, blk>>>(fcs_b, (float*)d_out);
}

// round 12
// speedup vs baseline: 1.0529x; 1.0529x over previous
#include <cuda_runtime.h>
#include <cuda_fp16.h>
#include <cstdint>

typedef __half h16;

#define BATCH 32768
#define NIMG  5
#define DIM   512
#define DCAT  600
#define M5    (BATCH * NIMG)
#define TS    (BATCH * 200)

#define WSCALE   128.0f      // weight pre-scale (keeps h1 out of fp16 subnormals)
#define IWSCALE  (1.0f / 128.0f)

// ---- fp32 scratch ----
__device__ __align__(128) float g_tmp[4 * TS];
__device__ __align__(128) float g_c[BATCH * DCAT];
__device__ __align__(128) float g_h[BATCH * DCAT];
__device__ __align__(128) float g_ci[BATCH * DIM];
__device__ __align__(128) float g_u[BATCH * DIM];
__device__ __align__(128) float g_score[M5];

// ---- fp16 split planes (x = h0 + h1, ~24-bit total) ----
#define FPS  ((long long)BATCH * 2560)
#define CPS  ((long long)BATCH * 640)
#define CIPS ((long long)BATCH * 512)
__device__ __align__(128) h16 g_fa [2 * FPS];
__device__ __align__(128) h16 g_ca [2 * CPS];
__device__ __align__(128) h16 g_ha [2 * CPS];
__device__ __align__(128) h16 g_cia[2 * CIPS];
__device__ __align__(128) h16 g_w2a[2 * 200 * 1024];
__device__ __align__(128) h16 g_w3a[2 * 200 * 1536];
__device__ __align__(128) h16 g_w5a[2 * 200 * 2560];
__device__ __align__(128) h16 g_f1a[2 * 600 * 640];
__device__ __align__(128) h16 g_f2a[2 * 512 * 640];
__device__ __align__(128) h16 g_f0aa[2 * 512 * 512];
__device__ __align__(128) h16 g_f0ua[2 * 512 * 512];

// ---- portable PTX helpers (sm_80+ ISA only) ----
__device__ __forceinline__ uint32_t smem_u32(const void* p) {
    uint32_t a;
    asm("{ .reg .u64 t; cvta.to.shared.u64 t, %1; cvt.u32.u64 %0, t; }"
        : "=r"(a) : "l"(p));
    return a;
}
__device__ __forceinline__ void cp16(uint32_t saddr, const void* gaddr, uint32_t srcsz) {
    asm volatile("cp.async.cg.shared.global [%0], [%1], 16, %2;"
                 :: "r"(saddr), "l"(gaddr), "r"(srcsz));
}
__device__ __forceinline__ void ldm4(uint32_t& r0, uint32_t& r1, uint32_t& r2,
                                     uint32_t& r3, uint32_t addr) {
    asm volatile("ldmatrix.sync.aligned.m8n8.x4.shared.b16 {%0,%1,%2,%3}, [%4];"
                 : "=r"(r0), "=r"(r1), "=r"(r2), "=r"(r3) : "r"(addr));
}
__device__ __forceinline__ void mma16816(float* d, const uint32_t* a,
                                         const uint32_t* b) {
    asm volatile(
        "mma.sync.aligned.m16n8k16.row.col.f32.f16.f16.f32 "
        "{%0,%1,%2,%3}, {%4,%5,%6,%7}, {%8,%9}, {%0,%1,%2,%3};"
        : "+f"(d[0]), "+f"(d[1]), "+f"(d[2]), "+f"(d[3])
        : "r"(a[0]), "r"(a[1]), "r"(a[2]), "r"(a[3]), "r"(b[0]), "r"(b[1]));
}

// smem: 3-stage ring; per stage 2 A planes + 2 B planes, rows padded to 48B
#define PLANEB 6144            // 128 rows * 48 B
#define STAGEB (4 * PLANEB)    // 24576 B
#define SMT    (3 * STAGEB)    // 73728 B

// ---------------------------------------------------------------------------
// Tensor-core GEMM via fp16x2 split (Markidis), split accumulators:
//   accM <- a0*b0 ;  accC <- a0*b1 + a1*b0   (a1*b1 ~ 2^-24, dropped)
//   C = (accM + accC) * oscale  (+bias/relu/score per MODE)
//   B planes hold weights pre-scaled by WSCALE; oscale = IWSCALE.
//   MODE 0:+bias  1:+bias,relu  2:raw (+z offset on C)  3: fused score epilogue
// Requires: M%128==0, K%16==0.
// ---------------------------------------------------------------------------
template<int MODE>
__global__ void __launch_bounds__(256, 1) tgemm(
    const h16* __restrict__ A, long long aPS, int lda, long long aZ,
    const h16* __restrict__ B, long long bPS, int ldb,
    const float* __restrict__ bias,
    float* __restrict__ C, int ldc, long long cZ,
    int Nn, int K, float oscale,
    const float* __restrict__ u, const float* __restrict__ sw)
{
    extern __shared__ char smem[];
    const uint32_t sb = smem_u32(smem);
    const int tid  = threadIdx.x;
    const int lane = tid & 31, wid = tid >> 5;
    const int wm = wid >> 2, wn = wid & 3;          // 2 x 4 warp grid
    const int bm = blockIdx.x * 128, bn = blockIdx.y * 128;

    A += (long long)blockIdx.z * aZ;
    if (MODE == 2) C += (long long)blockIdx.z * cZ;

    float accM[4][4][4], accC[4][4][4];
#pragma unroll
    for (int i = 0; i < 4; i++)
#pragma unroll
        for (int j = 0; j < 4; j++)
#pragma unroll
            for (int r = 0; r < 4; r++) { accM[i][j][r] = 0.f; accC[i][j][r] = 0.f; }

    const int lrow = (tid & 255) >> 1, lhalf = tid & 1;

    const uint32_t aOff = (uint32_t)((wm * 64 + (lane & 15)) * 48 + (lane >> 4) * 16);
    const uint32_t bOff = (uint32_t)((wn * 32 + (lane & 7) + ((lane >> 4) & 1) * 8) * 48
                                     + ((lane >> 3) & 1) * 16);

    const int nch = K >> 4;

    auto load_chunk = [&](int s, int st) {
        const uint32_t base = sb + (uint32_t)st * STAGEB + lrow * 48 + lhalf * 16;
#pragma unroll
        for (int p = 0; p < 2; p++) {
            const h16* g = A + (long long)p * aPS +
                           (long long)(bm + lrow) * lda + s * 16 + lhalf * 8;
            cp16(base + p * PLANEB, g, 16);
        }
        const int n = bn + lrow;
        const bool ok = n < Nn;
#pragma unroll
        for (int p = 0; p < 2; p++) {
            const h16* g = B + (long long)p * bPS +
                           (long long)(ok ? n : 0) * ldb + s * 16 + lhalf * 8;
            cp16(base + (2 + p) * PLANEB, g, ok ? 16u : 0u);
        }
        asm volatile("cp.async.commit_group;");
    };

    // prefetch chunks 0,1 (always one commit per slot to keep group count fixed)
    if (0 < nch) load_chunk(0, 0); else asm volatile("cp.async.commit_group;");
    if (1 < nch) load_chunk(1, 1); else asm volatile("cp.async.commit_group;");

    for (int s = 0; s < nch; ++s) {
        const int st = s % 3;
        if (s + 2 < nch) load_chunk(s + 2, (s + 2) % 3);
        else             asm volatile("cp.async.commit_group;");
        asm volatile("cp.async.wait_group 2;");
        __syncthreads();

        const uint32_t stage = sb + (uint32_t)st * STAGEB;
        uint32_t af[4][4], b0r[4][2], b1r[4][2];
        // A plane 0 fragments
#pragma unroll
        for (int i = 0; i < 4; i++)
            ldm4(af[i][0], af[i][1], af[i][2], af[i][3],
                 stage + aOff + i * (16 * 48));
        // B plane 0 + plane 1 fragments
        ldm4(b0r[0][0], b0r[0][1], b0r[1][0], b0r[1][1], stage + 2 * PLANEB + bOff);
        ldm4(b0r[2][0], b0r[2][1], b0r[3][0], b0r[3][1], stage + 2 * PLANEB + bOff + 16 * 48);
        ldm4(b1r[0][0], b1r[0][1], b1r[1][0], b1r[1][1], stage + 3 * PLANEB + bOff);
        ldm4(b1r[2][0], b1r[2][1], b1r[3][0], b1r[3][1], stage + 3 * PLANEB + bOff + 16 * 48);

        // q0: a0*b0 -> accM ; q1: a0*b1 -> accC
#pragma unroll
        for (int i = 0; i < 4; i++)
#pragma unroll
            for (int j = 0; j < 4; j++) {
                mma16816(accM[i][j], af[i], b0r[j]);
                mma16816(accC[i][j], af[i], b1r[j]);
            }
        // reload af <- A plane 1 ; q2: a1*b0 -> accC
#pragma unroll
        for (int i = 0; i < 4; i++)
            ldm4(af[i][0], af[i][1], af[i][2], af[i][3],
                 stage + PLANEB + aOff + i * (16 * 48));
#pragma unroll
        for (int i = 0; i < 4; i++)
#pragma unroll
            for (int j = 0; j < 4; j++)
                mma16816(accC[i][j], af[i], b0r[j]);

        __syncthreads();
    }

    // ---- epilogue ----
    const int gr = lane >> 2, tig = lane & 3;
    if (MODE == 3) {
#pragma unroll
        for (int i = 0; i < 4; i++) {
            const int m1 = bm + wm * 64 + i * 16 + gr;
            const int m2 = m1 + 8;
            const float* u1 = u + (long long)(m1 / NIMG) * DIM;
            const float* u2 = u + (long long)(m2 / NIMG) * DIM;
            float s1 = 0.f, s2 = 0.f;
#pragma unroll
            for (int j = 0; j < 4; j++) {
                const int c = bn + wn * 32 + j * 8 + 2 * tig;
                float w0 = sw[c], w1 = sw[c + 1];
                float v;
                v = (accM[i][j][0] + accC[i][j][0]) * oscale + u1[c];     s1 += fmaxf(v, 0.f) * w0;
                v = (accM[i][j][1] + accC[i][j][1]) * oscale + u1[c + 1]; s1 += fmaxf(v, 0.f) * w1;
                v = (accM[i][j][2] + accC[i][j][2]) * oscale + u2[c];     s2 += fmaxf(v, 0.f) * w0;
                v = (accM[i][j][3] + accC[i][j][3]) * oscale + u2[c + 1]; s2 += fmaxf(v, 0.f) * w1;
            }
            s1 += __shfl_xor_sync(0xffffffffu, s1, 1);
            s1 += __shfl_xor_sync(0xffffffffu, s1, 2);
            s2 += __shfl_xor_sync(0xffffffffu, s2, 1);
            s2 += __shfl_xor_sync(0xffffffffu, s2, 2);
            if (tig == 0) {
                atomicAdd(&g_score[m1], s1);
                atomicAdd(&g_score[m2], s2);
            }
        }
    } else {
#pragma unroll
        for (int i = 0; i < 4; i++) {
            const int m1 = bm + wm * 64 + i * 16 + gr;
#pragma unroll
            for (int j = 0; j < 4; j++) {
                const int c = bn + wn * 32 + j * 8 + 2 * tig;
                if (c < Nn) {
                    float b0 = 0.f, b1 = 0.f;
                    if (MODE != 2) { b0 = bias[c]; b1 = bias[c + 1]; }
                    float v0 = (accM[i][j][0] + accC[i][j][0]) * oscale + b0;
                    float v1 = (accM[i][j][1] + accC[i][j][1]) * oscale + b1;
                    float v2 = (accM[i][j][2] + accC[i][j][2]) * oscale + b0;
                    float v3 = (accM[i][j][3] + accC[i][j][3]) * oscale + b1;
                    if (MODE == 1) {
                        v0 = fmaxf(v0, 0.f); v1 = fmaxf(v1, 0.f);
                        v2 = fmaxf(v2, 0.f); v3 = fmaxf(v3, 0.f);
                    }
                    *(float2*)&C[(long long)m1 * ldc + c]       = make_float2(v0, v1);
                    *(float2*)&C[(long long)(m1 + 8) * ldc + c] = make_float2(v2, v3);
                }
            }
        }
    }
}

// ---------------------------------------------------------------------------
// fp32 -> 2 fp16 planes (RN split, ~24 bits). Optional pre-scale, row padding.
// ---------------------------------------------------------------------------
__global__ void split2(const float* __restrict__ src, h16* __restrict__ dst,
                       long long ps, long long total, int srcCols, int dstCols,
                       float preScale)
{
    long long idx = (long long)blockIdx.x * blockDim.x + threadIdx.x;
    if (idx >= total) return;
    float x;
    if (srcCols == dstCols) x = src[idx];
    else {
        long long r = idx / dstCols;
        int k = (int)(idx - r * dstCols);
        x = (k < srcCols) ? src[r * srcCols + k] : 0.f;
    }
    x *= preScale;
    h16 h0 = __float2half_rn(x);
    h16 h1 = __float2half_rn(x - __half2float(h0));
    dst[idx] = h0; dst[ps + idx] = h1;
}

// Transpose+split: src [K,N] fp32 -> dst [N,Kpad] fp16 pairs (zero K-pad).
__global__ void split2T(const float* __restrict__ src, h16* __restrict__ dst,
                        long long ps, int N, int K, int Kpad, float preScale)
{
    int idx = blockIdx.x * blockDim.x + threadIdx.x;
    if (idx >= N * Kpad) return;
    int n = idx / Kpad, k = idx % Kpad;
    float x = (k < K) ? src[(long long)k * N + n] * preScale : 0.f;
    h16 h0 = __float2half_rn(x);
    h16 h1 = __float2half_rn(x - __half2float(h0));
    dst[idx] = h0; dst[ps + idx] = h1;
}

__global__ void conv_reduce(const float* __restrict__ bias, int T, int coff)
{
    int idx = blockIdx.x * blockDim.x + threadIdx.x;
    if (idx >= BATCH * 200) return;
    int c = idx % 200, n = idx / 200;
    float v = g_tmp[idx];
    for (int t = 1; t < T; t++) v = fmaxf(v, g_tmp[(size_t)t * TS + idx]);
    g_c[(size_t)n * DCAT + coff + c] = fmaxf(v + bias[c], 0.f);
}

__global__ void zero_score()
{
    int i = blockIdx.x * blockDim.x + threadIdx.x;
    if (i < M5) g_score[i] = 0.f;
}

__global__ void finalize_f32(const float* __restrict__ fcs_b, float* __restrict__ out)
{
    int n = blockIdx.x * blockDim.x + threadIdx.x;
    if (n >= BATCH) return;
    float fb = fcs_b[0];
    float s[5];
#pragma unroll
    for (int i = 0; i < 5; i++) s[i] = g_score[n * 5 + i] + fb;
#pragma unroll
    for (int i = 0; i < 5; i++) {
        int si = n * 5 + i;
        out[si] = s[i];
        int r = 0;
#pragma unroll
        for (int j = 0; j < 5; j++)
            r += (s[j] > s[i]) || ((s[j] == s[i]) && (j < i));
        out[M5 + si] = (float)r;
    }
}

extern "C" void kernel_launch(void* const* d_in, const int* in_sizes, int n_in,
                              void* d_out, int out_size)
{
    const float* feats = (const float*)d_in[0];
    const float* w2    = (const float*)d_in[1];
    const float* b2    = (const float*)d_in[2];
    const float* w3    = (const float*)d_in[3];
    const float* b3    = (const float*)d_in[4];
    const float* w5    = (const float*)d_in[5];
    const float* b5    = (const float*)d_in[6];
    const float* fc1_w = (const float*)d_in[7];
    const float* fc1_b = (const float*)d_in[8];
    const float* fc2_w = (const float*)d_in[9];
    const float* fc2_b = (const float*)d_in[10];
    const float* fc0_w = (const float*)d_in[11];
    const float* fc0_b = (const float*)d_in[12];
    const float* fcs_w = (const float*)d_in[13];
    const float* fcs_b = (const float*)d_in[14];

    float *pt, *pc, *ph, *pci, *pu;
    cudaGetSymbolAddress((void**)&pt,  g_tmp);
    cudaGetSymbolAddress((void**)&pc,  g_c);
    cudaGetSymbolAddress((void**)&ph,  g_h);
    cudaGetSymbolAddress((void**)&pci, g_ci);
    cudaGetSymbolAddress((void**)&pu,  g_u);
    h16 *fa, *ca, *ha, *cia, *w2a, *w3a, *w5a, *f1a, *f2a, *f0aa, *f0ua;
    cudaGetSymbolAddress((void**)&fa,   g_fa);
    cudaGetSymbolAddress((void**)&ca,   g_ca);
    cudaGetSymbolAddress((void**)&ha,   g_ha);
    cudaGetSymbolAddress((void**)&cia,  g_cia);
    cudaGetSymbolAddress((void**)&w2a,  g_w2a);
    cudaGetSymbolAddress((void**)&w3a,  g_w3a);
    cudaGetSymbolAddress((void**)&w5a,  g_w5a);
    cudaGetSymbolAddress((void**)&f1a,  g_f1a);
    cudaGetSymbolAddress((void**)&f2a,  g_f2a);
    cudaGetSymbolAddress((void**)&f0aa, g_f0aa);
    cudaGetSymbolAddress((void**)&f0ua, g_f0ua);

    cudaFuncSetAttribute(tgemm<0>, cudaFuncAttributeMaxDynamicSharedMemorySize, SMT);
    cudaFuncSetAttribute(tgemm<1>, cudaFuncAttributeMaxDynamicSharedMemorySize, SMT);
    cudaFuncSetAttribute(tgemm<2>, cudaFuncAttributeMaxDynamicSharedMemorySize, SMT);
    cudaFuncSetAttribute(tgemm<3>, cudaFuncAttributeMaxDynamicSharedMemorySize, SMT);

    dim3 blk(256);
    const int MB = BATCH / 128;

    // ---- splits (activations preScale=1, weights preScale=WSCALE) ----
    split2<<<(int)((83886080LL + 255) / 256), blk>>>(feats, fa, FPS, 83886080LL,
                                                     2560, 2560, 1.f);
    split2<<<(204800 + 255) / 256, blk>>>(w2, w2a, 200 * 1024, 204800, 1024, 1024, WSCALE);
    split2<<<(307200 + 255) / 256, blk>>>(w3, w3a, 200 * 1536, 307200, 1536, 1536, WSCALE);
    split2<<<(512000 + 255) / 256, blk>>>(w5, w5a, 200 * 2560, 512000, 2560, 2560, WSCALE);
    split2T<<<(600 * 640 + 255) / 256, blk>>>(fc1_w, f1a, 600 * 640, 600, 600, 640, WSCALE);
    split2T<<<(512 * 640 + 255) / 256, blk>>>(fc2_w, f2a, 512 * 640, 512, 600, 640, WSCALE);
    split2T<<<(512 * 512 + 255) / 256, blk>>>(fc0_w, f0aa, 512 * 512, 512, 512, 512, WSCALE);
    split2T<<<(512 * 512 + 255) / 256, blk>>>(fc0_w + (size_t)DIM * DIM, f0ua,
                                              512 * 512, 512, 512, 512, WSCALE);

    // ---- conv blocks ----
    tgemm<2><<<dim3(MB, 2, 4), blk, SMT>>>(fa, FPS, 2560, 512,
        w2a, 200 * 1024, 1024, nullptr, pt, 200, TS, 200, 1024, IWSCALE, nullptr, nullptr);
    conv_reduce<<<(BATCH * 200 + 255) / 256, blk>>>(b2, 4, 0);

    tgemm<2><<<dim3(MB, 2, 3), blk, SMT>>>(fa, FPS, 2560, 512,
        w3a, 200 * 1536, 1536, nullptr, pt, 200, TS, 200, 1536, IWSCALE, nullptr, nullptr);
    conv_reduce<<<(BATCH * 200 + 255) / 256, blk>>>(b3, 3, 200);

    tgemm<1><<<dim3(MB, 2, 1), blk, SMT>>>(fa, FPS, 2560, 0,
        w5a, 200 * 2560, 2560, b5, pc + 400, DCAT, 0, 200, 2560, IWSCALE, nullptr, nullptr);

    // ---- fc1 ----
    split2<<<(int)(((long long)BATCH * 640 + 255) / 256), blk>>>(pc, ca, CPS,
        (long long)BATCH * 640, 600, 640, 1.f);
    tgemm<1><<<dim3(MB, 5, 1), blk, SMT>>>(ca, CPS, 640, 0,
        f1a, 600 * 640, 640, fc1_b, ph, DCAT, 0, 600, 640, IWSCALE, nullptr, nullptr);

    // ---- fc2 ----
    split2<<<(int)(((long long)BATCH * 640 + 255) / 256), blk>>>(ph, ha, CPS,
        (long long)BATCH * 640, 600, 640, 1.f);
    tgemm<0><<<dim3(MB, 4, 1), blk, SMT>>>(ha, CPS, 640, 0,
        f2a, 512 * 640, 640, fc2_b, pci, DIM, 0, 512, 640, IWSCALE, nullptr, nullptr);

    // ---- u = ci @ fc0_w[512:] + fc0_b ----
    split2<<<(int)(((long long)BATCH * 512 + 255) / 256), blk>>>(pci, cia, CIPS,
        (long long)BATCH * 512, 512, 512, 1.f);
    tgemm<0><<<dim3(MB, 4, 1), blk, SMT>>>(cia, CIPS, 512, 0,
        f0ua, 512 * 512, 512, fc0_b, pu, DIM, 0, 512, 512, IWSCALE, nullptr, nullptr);

    // ---- fused score GEMM ----
    zero_score<<<(M5 + 255) / 256, blk>>>();
    tgemm<3><<<dim3(M5 / 128, 4, 1), blk, SMT>>>(fa, FPS, 512, 0,
        f0aa, 512 * 512, 512, nullptr, nullptr, 0, 0, 512, 512, IWSCALE, pu, fcs_w);

    finalize_f32<<<(BATCH + 255) / 256, blk>>>(fcs_b, (float*)d_out);
}

// round 13
// speedup vs baseline: 1.9687x; 1.8698x over previous
#include <cuda_runtime.h>
#include <cuda_fp16.h>
#include <cstdint>

typedef __half h16;

#define BATCH 32768
#define NIMG  5
#define DIM   512
#define DCAT  600
#define M5    (BATCH * NIMG)
#define TS    (BATCH * 200)

#define WSCALE   128.0f
#define IWSCALE  (1.0f / 128.0f)

// ---- fp32 scratch ----
__device__ __align__(128) float g_tmp[4 * TS];
__device__ __align__(128) float g_c[BATCH * DCAT];
__device__ __align__(128) float g_h[BATCH * DCAT];
__device__ __align__(128) float g_ci[BATCH * DIM];
__device__ __align__(128) float g_u[BATCH * DIM];
__device__ __align__(128) float g_score[M5];

// ---- fp16 split planes (x = h0 + h1, ~24-bit total) ----
#define FPS  ((long long)BATCH * 2560)
#define CPS  ((long long)BATCH * 640)
#define CIPS ((long long)BATCH * 512)
__device__ __align__(128) h16 g_fa [2 * FPS];
__device__ __align__(128) h16 g_ca [2 * CPS];
__device__ __align__(128) h16 g_ha [2 * CPS];
__device__ __align__(128) h16 g_cia[2 * CIPS];
__device__ __align__(128) h16 g_w2a[2 * 200 * 1024];
__device__ __align__(128) h16 g_w3a[2 * 200 * 1536];
__device__ __align__(128) h16 g_w5a[2 * 200 * 2560];
__device__ __align__(128) h16 g_f1a[2 * 600 * 640];
__device__ __align__(128) h16 g_f2a[2 * 512 * 640];
__device__ __align__(128) h16 g_f0aa[2 * 512 * 512];
__device__ __align__(128) h16 g_f0ua[2 * 512 * 512];

// ---- portable PTX helpers (sm_80+ ISA only) ----
__device__ __forceinline__ uint32_t smem_u32(const void* p) {
    uint32_t a;
    asm("{ .reg .u64 t; cvta.to.shared.u64 t, %1; cvt.u32.u64 %0, t; }"
        : "=r"(a) : "l"(p));
    return a;
}
__device__ __forceinline__ void cp16(uint32_t saddr, const void* gaddr, uint32_t srcsz) {
    asm volatile("cp.async.cg.shared.global [%0], [%1], 16, %2;"
                 :: "r"(saddr), "l"(gaddr), "r"(srcsz));
}
__device__ __forceinline__ void ldm4(uint32_t& r0, uint32_t& r1, uint32_t& r2,
                                     uint32_t& r3, uint32_t addr) {
    asm volatile("ldmatrix.sync.aligned.m8n8.x4.shared.b16 {%0,%1,%2,%3}, [%4];"
                 : "=r"(r0), "=r"(r1), "=r"(r2), "=r"(r3) : "r"(addr));
}
__device__ __forceinline__ void mma16816(float* d, const uint32_t* a,
                                         const uint32_t* b) {
    asm volatile(
        "mma.sync.aligned.m16n8k16.row.col.f32.f16.f16.f32 "
        "{%0,%1,%2,%3}, {%4,%5,%6,%7}, {%8,%9}, {%0,%1,%2,%3};"
        : "+f"(d[0]), "+f"(d[1]), "+f"(d[2]), "+f"(d[3])
        : "r"(a[0]), "r"(a[1]), "r"(a[2]), "r"(a[3]), "r"(b[0]), "r"(b[1]));
}

// smem: 3-stage ring; per stage 2 A planes + 2 B planes of k32 (rows 64B->80B)
#define PLANEB 10240           // 128 rows * 80 B
#define STAGEB (4 * PLANEB)    // 40960 B
#define SMT    (3 * STAGEB)    // 122880 B

// ---------------------------------------------------------------------------
// Tensor-core GEMM, fp16x2 split (Markidis), dual accumulators.
//   GRID: blockIdx.x = N-block (A-sharing CTAs adjacent), blockIdx.y = M-block,
//         blockIdx.z = conv window.
//   K consumed in chunks of 32 (two k16 sub-steps per barrier).
//   MODE 0:+bias  1:+bias,relu  2:raw (+z offset on C)  3: fused score epilogue
// Requires: M%128==0, K%32==0.
// ---------------------------------------------------------------------------
template<int MODE>
__global__ void __launch_bounds__(256, 1) tgemm(
    const h16* __restrict__ A, long long aPS, int lda, long long aZ,
    const h16* __restrict__ B, long long bPS, int ldb,
    const float* __restrict__ bias,
    float* __restrict__ C, int ldc, long long cZ,
    int Nn, int K, float oscale,
    const float* __restrict__ u, const float* __restrict__ sw)
{
    extern __shared__ char smem[];
    const uint32_t sb = smem_u32(smem);
    const int tid  = threadIdx.x;
    const int lane = tid & 31, wid = tid >> 5;
    const int wm = wid >> 2, wn = wid & 3;            // 2 x 4 warp grid
    const int bn = blockIdx.x * 128, bm = blockIdx.y * 128;

    A += (long long)blockIdx.z * aZ;
    if (MODE == 2) C += (long long)blockIdx.z * cZ;

    float accM[4][4][4], accC[4][4][4];
#pragma unroll
    for (int i = 0; i < 4; i++)
#pragma unroll
        for (int j = 0; j < 4; j++)
#pragma unroll
            for (int r = 0; r < 4; r++) { accM[i][j][r] = 0.f; accC[i][j][r] = 0.f; }

    const uint32_t aOff = (uint32_t)((wm * 64 + (lane & 15)) * 80 + (lane >> 4) * 16);
    const uint32_t bOff = (uint32_t)((wn * 32 + (lane & 7) + ((lane >> 4) & 1) * 8) * 80
                                     + ((lane >> 3) & 1) * 16);

    const int nch = K >> 5;

    // loader: 2048 16B-vectors per stage (4 planes x 128 rows x 4 segs), 8/thread
    auto load_chunk = [&](int s, int st) {
        const uint32_t base = sb + (uint32_t)st * STAGEB;
#pragma unroll
        for (int it = 0; it < 8; it++) {
            const int v = tid + it * 256;
            const int plane = v >> 9;           // 0,1 = A planes; 2,3 = B planes
            const int rem = v & 511;
            const int row = rem >> 2, seg = rem & 3;
            const uint32_t soff = base + plane * PLANEB + row * 80 + seg * 16;
            if (plane < 2) {
                const h16* g = A + (long long)plane * aPS +
                               (long long)(bm + row) * lda + s * 32 + seg * 8;
                cp16(soff, g, 16);
            } else {
                const int n = bn + row;
                const bool ok = n < Nn;
                const h16* g = B + (long long)(plane - 2) * bPS +
                               (long long)(ok ? n : 0) * ldb + s * 32 + seg * 8;
                cp16(soff, g, ok ? 16u : 0u);
            }
        }
        asm volatile("cp.async.commit_group;");
    };

    if (0 < nch) load_chunk(0, 0); else asm volatile("cp.async.commit_group;");
    if (1 < nch) load_chunk(1, 1); else asm volatile("cp.async.commit_group;");

    for (int s = 0; s < nch; ++s) {
        const int st = s % 3;
        if (s + 2 < nch) load_chunk(s + 2, (s + 2) % 3);
        else             asm volatile("cp.async.commit_group;");
        asm volatile("cp.async.wait_group 2;");
        __syncthreads();

        const uint32_t stage = sb + (uint32_t)st * STAGEB;
#pragma unroll
        for (int kk = 0; kk < 2; kk++) {
            const uint32_t ko = kk * 32;          // 16 cols = 32 B
            uint32_t af[4][4], b0r[4][2], b1r[4][2];
#pragma unroll
            for (int i = 0; i < 4; i++)
                ldm4(af[i][0], af[i][1], af[i][2], af[i][3],
                     stage + aOff + ko + i * (16 * 80));
            ldm4(b0r[0][0], b0r[0][1], b0r[1][0], b0r[1][1],
                 stage + 2 * PLANEB + bOff + ko);
            ldm4(b0r[2][0], b0r[2][1], b0r[3][0], b0r[3][1],
                 stage + 2 * PLANEB + bOff + ko + 16 * 80);
            ldm4(b1r[0][0], b1r[0][1], b1r[1][0], b1r[1][1],
                 stage + 3 * PLANEB + bOff + ko);
            ldm4(b1r[2][0], b1r[2][1], b1r[3][0], b1r[3][1],
                 stage + 3 * PLANEB + bOff + ko + 16 * 80);

            // a0*b0 -> accM ; a0*b1 -> accC
#pragma unroll
            for (int i = 0; i < 4; i++)
#pragma unroll
                for (int j = 0; j < 4; j++) {
                    mma16816(accM[i][j], af[i], b0r[j]);
                    mma16816(accC[i][j], af[i], b1r[j]);
                }
            // af <- A plane 1 ; a1*b0 -> accC
#pragma unroll
            for (int i = 0; i < 4; i++)
                ldm4(af[i][0], af[i][1], af[i][2], af[i][3],
                     stage + PLANEB + aOff + ko + i * (16 * 80));
#pragma unroll
            for (int i = 0; i < 4; i++)
#pragma unroll
                for (int j = 0; j < 4; j++)
                    mma16816(accC[i][j], af[i], b0r[j]);
        }
        __syncthreads();
    }

    // ---- epilogue ----
    const int gr = lane >> 2, tig = lane & 3;
    if (MODE == 3) {
#pragma unroll
        for (int i = 0; i < 4; i++) {
            const int m1 = bm + wm * 64 + i * 16 + gr;
            const int m2 = m1 + 8;
            const float* u1 = u + (long long)(m1 / NIMG) * DIM;
            const float* u2 = u + (long long)(m2 / NIMG) * DIM;
            float s1 = 0.f, s2 = 0.f;
#pragma unroll
            for (int j = 0; j < 4; j++) {
                const int c = bn + wn * 32 + j * 8 + 2 * tig;
                float w0 = sw[c], w1 = sw[c + 1];
                float v;
                v = (accM[i][j][0] + accC[i][j][0]) * oscale + u1[c];     s1 += fmaxf(v, 0.f) * w0;
                v = (accM[i][j][1] + accC[i][j][1]) * oscale + u1[c + 1]; s1 += fmaxf(v, 0.f) * w1;
                v = (accM[i][j][2] + accC[i][j][2]) * oscale + u2[c];     s2 += fmaxf(v, 0.f) * w0;
                v = (accM[i][j][3] + accC[i][j][3]) * oscale + u2[c + 1]; s2 += fmaxf(v, 0.f) * w1;
            }
            s1 += __shfl_xor_sync(0xffffffffu, s1, 1);
            s1 += __shfl_xor_sync(0xffffffffu, s1, 2);
            s2 += __shfl_xor_sync(0xffffffffu, s2, 1);
            s2 += __shfl_xor_sync(0xffffffffu, s2, 2);
            if (tig == 0) {
                atomicAdd(&g_score[m1], s1);
                atomicAdd(&g_score[m2], s2);
            }
        }
    } else {
#pragma unroll
        for (int i = 0; i < 4; i++) {
            const int m1 = bm + wm * 64 + i * 16 + gr;
#pragma unroll
            for (int j = 0; j < 4; j++) {
                const int c = bn + wn * 32 + j * 8 + 2 * tig;
                if (c < Nn) {
                    float b0 = 0.f, b1 = 0.f;
                    if (MODE != 2) { b0 = bias[c]; b1 = bias[c + 1]; }
                    float v0 = (accM[i][j][0] + accC[i][j][0]) * oscale + b0;
                    float v1 = (accM[i][j][1] + accC[i][j][1]) * oscale + b1;
                    float v2 = (accM[i][j][2] + accC[i][j][2]) * oscale + b0;
                    float v3 = (accM[i][j][3] + accC[i][j][3]) * oscale + b1;
                    if (MODE == 1) {
                        v0 = fmaxf(v0, 0.f); v1 = fmaxf(v1, 0.f);
                        v2 = fmaxf(v2, 0.f); v3 = fmaxf(v3, 0.f);
                    }
                    *(float2*)&C[(long long)m1 * ldc + c]       = make_float2(v0, v1);
                    *(float2*)&C[(long long)(m1 + 8) * ldc + c] = make_float2(v2, v3);
                }
            }
        }
    }
}

// ---------------------------------------------------------------------------
__global__ void split2(const float* __restrict__ src, h16* __restrict__ dst,
                       long long ps, long long total, int srcCols, int dstCols,
                       float preScale)
{
    long long idx = (long long)blockIdx.x * blockDim.x + threadIdx.x;
    if (idx >= total) return;
    float x;
    if (srcCols == dstCols) x = src[idx];
    else {
        long long r = idx / dstCols;
        int k = (int)(idx - r * dstCols);
        x = (k < srcCols) ? src[r * srcCols + k] : 0.f;
    }
    x *= preScale;
    h16 h0 = __float2half_rn(x);
    h16 h1 = __float2half_rn(x - __half2float(h0));
    dst[idx] = h0; dst[ps + idx] = h1;
}

__global__ void split2T(const float* __restrict__ src, h16* __restrict__ dst,
                        long long ps, int N, int K, int Kpad, float preScale)
{
    int idx = blockIdx.x * blockDim.x + threadIdx.x;
    if (idx >= N * Kpad) return;
    int n = idx / Kpad, k = idx % Kpad;
    float x = (k < K) ? src[(long long)k * N + n] * preScale : 0.f;
    h16 h0 = __float2half_rn(x);
    h16 h1 = __float2half_rn(x - __half2float(h0));
    dst[idx] = h0; dst[ps + idx] = h1;
}

__global__ void conv_reduce(const float* __restrict__ bias, int T, int coff)
{
    int idx = blockIdx.x * blockDim.x + threadIdx.x;
    if (idx >= BATCH * 200) return;
    int c = idx % 200, n = idx / 200;
    float v = g_tmp[idx];
    for (int t = 1; t < T; t++) v = fmaxf(v, g_tmp[(size_t)t * TS + idx]);
    g_c[(size_t)n * DCAT + coff + c] = fmaxf(v + bias[c], 0.f);
}

__global__ void zero_score()
{
    int i = blockIdx.x * blockDim.x + threadIdx.x;
    if (i < M5) g_score[i] = 0.f;
}

__global__ void finalize_f32(const float* __restrict__ fcs_b, float* __restrict__ out)
{
    int n = blockIdx.x * blockDim.x + threadIdx.x;
    if (n >= BATCH) return;
    float fb = fcs_b[0];
    float s[5];
#pragma unroll
    for (int i = 0; i < 5; i++) s[i] = g_score[n * 5 + i] + fb;
#pragma unroll
    for (int i = 0; i < 5; i++) {
        int si = n * 5 + i;
        out[si] = s[i];
        int r = 0;
#pragma unroll
        for (int j = 0; j < 5; j++)
            r += (s[j] > s[i]) || ((s[j] == s[i]) && (j < i));
        out[M5 + si] = (float)r;
    }
}

extern "C" void kernel_launch(void* const* d_in, const int* in_sizes, int n_in,
                              void* d_out, int out_size)
{
    const float* feats = (const float*)d_in[0];
    const float* w2    = (const float*)d_in[1];
    const float* b2    = (const float*)d_in[2];
    const float* w3    = (const float*)d_in[3];
    const float* b3    = (const float*)d_in[4];
    const float* w5    = (const float*)d_in[5];
    const float* b5    = (const float*)d_in[6];
    const float* fc1_w = (const float*)d_in[7];
    const float* fc1_b = (const float*)d_in[8];
    const float* fc2_w = (const float*)d_in[9];
    const float* fc2_b = (const float*)d_in[10];
    const float* fc0_w = (const float*)d_in[11];
    const float* fc0_b = (const float*)d_in[12];
    const float* fcs_w = (const float*)d_in[13];
    const float* fcs_b = (const float*)d_in[14];

    float *pt, *pc, *ph, *pci, *pu;
    cudaGetSymbolAddress((void**)&pt,  g_tmp);
    cudaGetSymbolAddress((void**)&pc,  g_c);
    cudaGetSymbolAddress((void**)&ph,  g_h);
    cudaGetSymbolAddress((void**)&pci, g_ci);
    cudaGetSymbolAddress((void**)&pu,  g_u);
    h16 *fa, *ca, *ha, *cia, *w2a, *w3a, *w5a, *f1a, *f2a, *f0aa, *f0ua;
    cudaGetSymbolAddress((void**)&fa,   g_fa);
    cudaGetSymbolAddress((void**)&ca,   g_ca);
    cudaGetSymbolAddress((void**)&ha,   g_ha);
    cudaGetSymbolAddress((void**)&cia,  g_cia);
    cudaGetSymbolAddress((void**)&w2a,  g_w2a);
    cudaGetSymbolAddress((void**)&w3a,  g_w3a);
    cudaGetSymbolAddress((void**)&w5a,  g_w5a);
    cudaGetSymbolAddress((void**)&f1a,  g_f1a);
    cudaGetSymbolAddress((void**)&f2a,  g_f2a);
    cudaGetSymbolAddress((void**)&f0aa, g_f0aa);
    cudaGetSymbolAddress((void**)&f0ua, g_f0ua);

    cudaFuncSetAttribute(tgemm<0>, cudaFuncAttributeMaxDynamicSharedMemorySize, SMT);
    cudaFuncSetAttribute(tgemm<1>, cudaFuncAttributeMaxDynamicSharedMemorySize, SMT);
    cudaFuncSetAttribute(tgemm<2>, cudaFuncAttributeMaxDynamicSharedMemorySize, SMT);
    cudaFuncSetAttribute(tgemm<3>, cudaFuncAttributeMaxDynamicSharedMemorySize, SMT);

    dim3 blk(256);
    const int MB = BATCH / 128;

    // ---- splits (activations preScale=1, weights preScale=WSCALE) ----
    split2<<<(int)((83886080LL + 255) / 256), blk>>>(feats, fa, FPS, 83886080LL,
                                                     2560, 2560, 1.f);
    split2<<<(204800 + 255) / 256, blk>>>(w2, w2a, 200 * 1024, 204800, 1024, 1024, WSCALE);
    split2<<<(307200 + 255) / 256, blk>>>(w3, w3a, 200 * 1536, 307200, 1536, 1536, WSCALE);
    split2<<<(512000 + 255) / 256, blk>>>(w5, w5a, 200 * 2560, 512000, 2560, 2560, WSCALE);
    split2T<<<(600 * 640 + 255) / 256, blk>>>(fc1_w, f1a, 600 * 640, 600, 600, 640, WSCALE);
    split2T<<<(512 * 640 + 255) / 256, blk>>>(fc2_w, f2a, 512 * 640, 512, 600, 640, WSCALE);
    split2T<<<(512 * 512 + 255) / 256, blk>>>(fc0_w, f0aa, 512 * 512, 512, 512, 512, WSCALE);
    split2T<<<(512 * 512 + 255) / 256, blk>>>(fc0_w + (size_t)DIM * DIM, f0ua,
                                              512 * 512, 512, 512, 512, WSCALE);

    // ---- conv blocks (grid: x=N-block, y=M-block, z=window) ----
    tgemm<2><<<dim3(2, MB, 4), blk, SMT>>>(fa, FPS, 2560, 512,
        w2a, 200 * 1024, 1024, nullptr, pt, 200, TS, 200, 1024, IWSCALE, nullptr, nullptr);
    conv_reduce<<<(BATCH * 200 + 255) / 256, blk>>>(b2, 4, 0);

    tgemm<2><<<dim3(2, MB, 3), blk, SMT>>>(fa, FPS, 2560, 512,
        w3a, 200 * 1536, 1536, nullptr, pt, 200, TS, 200, 1536, IWSCALE, nullptr, nullptr);
    conv_reduce<<<(BATCH * 200 + 255) / 256, blk>>>(b3, 3, 200);

    tgemm<1><<<dim3(2, MB, 1), blk, SMT>>>(fa, FPS, 2560, 0,
        w5a, 200 * 2560, 2560, b5, pc + 400, DCAT, 0, 200, 2560, IWSCALE, nullptr, nullptr);

    // ---- fc1 ----
    split2<<<(int)(((long long)BATCH * 640 + 255) / 256), blk>>>(pc, ca, CPS,
        (long long)BATCH * 640, 600, 640, 1.f);
    tgemm<1><<<dim3(5, MB, 1), blk, SMT>>>(ca, CPS, 640, 0,
        f1a, 600 * 640, 640, fc1_b, ph, DCAT, 0, 600, 640, IWSCALE, nullptr, nullptr);

    // ---- fc2 ----
    split2<<<(int)(((long long)BATCH * 640 + 255) / 256), blk>>>(ph, ha, CPS,
        (long long)BATCH * 640, 600, 640, 1.f);
    tgemm<0><<<dim3(4, MB, 1), blk, SMT>>>(ha, CPS, 640, 0,
        f2a, 512 * 640, 640, fc2_b, pci, DIM, 0, 512, 640, IWSCALE, nullptr, nullptr);

    // ---- u = ci @ fc0_w[512:] + fc0_b ----
    split2<<<(int)(((long long)BATCH * 512 + 255) / 256), blk>>>(pci, cia, CIPS,
        (long long)BATCH * 512, 512, 512, 1.f);
    tgemm<0><<<dim3(4, MB, 1), blk, SMT>>>(cia, CIPS, 512, 0,
        f0ua, 512 * 512, 512, fc0_b, pu, DIM, 0, 512, 512, IWSCALE, nullptr, nullptr);

    // ---- fused score GEMM ----
    zero_score<<<(M5 + 255) / 256, blk>>>();
    tgemm<3><<<dim3(4, M5 / 128, 1), blk, SMT>>>(fa, FPS, 512, 0,
        f0aa, 512 * 512, 512, nullptr, nullptr, 0, 0, 512, 512, IWSCALE, pu, fcs_w);

    finalize_f32<<<(BATCH + 255) / 256, blk>>>(fcs_b, (float*)d_out);
}

// round 14
// speedup vs baseline: 2.0611x; 1.0469x over previous
#include <cuda_runtime.h>
#include <cuda_fp16.h>
#include <cstdint>

typedef __half h16;

#define BATCH 32768
#define NIMG  5
#define DIM   512
#define DCAT  600
#define M5    (BATCH * NIMG)
#define TS    (BATCH * 200)

#define WSCALE   128.0f
#define IWSCALE  (1.0f / 128.0f)

// ---- fp32 scratch ----
__device__ __align__(128) float g_tmp[4 * TS];
__device__ __align__(128) float g_u[BATCH * DIM];
__device__ __align__(128) float g_score[M5];

// ---- fp16 split planes (x = h0 + h1, ~24-bit total) ----
#define FPS  ((long long)BATCH * 2560)
#define CPS  ((long long)BATCH * 640)
#define CIPS ((long long)BATCH * 512)
__device__ __align__(128) h16 g_fa [2 * FPS];
__device__ __align__(128) h16 g_ca [2 * CPS];     // conv concat, 640-wide
__device__ __align__(128) h16 g_ha [2 * CPS];     // relu(fc1), 640-wide
__device__ __align__(128) h16 g_cia[2 * CIPS];    // fc2 out, 512-wide
__device__ __align__(128) h16 g_w2a[2 * 200 * 1024];
__device__ __align__(128) h16 g_w3a[2 * 200 * 1536];
__device__ __align__(128) h16 g_w5a[2 * 200 * 2560];
__device__ __align__(128) h16 g_f1a[2 * 600 * 640];
__device__ __align__(128) h16 g_f2a[2 * 512 * 640];
__device__ __align__(128) h16 g_f0aa[2 * 512 * 512];
__device__ __align__(128) h16 g_f0ua[2 * 512 * 512];

// ---- portable PTX helpers (sm_80+ ISA only) ----
__device__ __forceinline__ uint32_t smem_u32(const void* p) {
    uint32_t a;
    asm("{ .reg .u64 t; cvta.to.shared.u64 t, %1; cvt.u32.u64 %0, t; }"
        : "=r"(a) : "l"(p));
    return a;
}
__device__ __forceinline__ void cp16(uint32_t saddr, const void* gaddr, uint32_t srcsz) {
    asm volatile("cp.async.cg.shared.global [%0], [%1], 16, %2;"
                 :: "r"(saddr), "l"(gaddr), "r"(srcsz));
}
__device__ __forceinline__ void ldm4(uint32_t& r0, uint32_t& r1, uint32_t& r2,
                                     uint32_t& r3, uint32_t addr) {
    asm volatile("ldmatrix.sync.aligned.m8n8.x4.shared.b16 {%0,%1,%2,%3}, [%4];"
                 : "=r"(r0), "=r"(r1), "=r"(r2), "=r"(r3) : "r"(addr));
}
__device__ __forceinline__ void mma16816(float* d, const uint32_t* a,
                                         const uint32_t* b) {
    asm volatile(
        "mma.sync.aligned.m16n8k16.row.col.f32.f16.f16.f32 "
        "{%0,%1,%2,%3}, {%4,%5,%6,%7}, {%8,%9}, {%0,%1,%2,%3};"
        : "+f"(d[0]), "+f"(d[1]), "+f"(d[2]), "+f"(d[3])
        : "r"(a[0]), "r"(a[1]), "r"(a[2]), "r"(a[3]), "r"(b[0]), "r"(b[1]));
}
__device__ __forceinline__ void split_store(h16* dst, long long dPS,
                                            long long idx, float v0, float v1) {
    h16 a0 = __float2half_rn(v0);
    h16 b0 = __float2half_rn(v1);
    h16 a1 = __float2half_rn(v0 - __half2float(a0));
    h16 b1 = __float2half_rn(v1 - __half2float(b0));
    *(__half2*)&dst[idx]       = __halves2half2(a0, b0);
    *(__half2*)&dst[dPS + idx] = __halves2half2(a1, b1);
}

// smem: 3-stage ring; per stage 2 A planes + 2 B planes of k32 (rows 64B->80B)
#define PLANEB 10240           // 128 rows * 80 B
#define STAGEB (4 * PLANEB)    // 40960 B
#define SMT    (3 * STAGEB)    // 122880 B

// ---------------------------------------------------------------------------
// Tensor-core GEMM, fp16x2 split (Markidis), dual accumulators.
//   GRID: blockIdx.x = N-block, blockIdx.y = M-block, blockIdx.z = conv window.
//   MODE 0:+bias->f32  2:raw->f32(+z C offset)  3:fused score
//   MODE 4:+bias,relu->split planes  5:+bias->split planes
//   (4/5 zero-fill cols in [Nn, wlim) for K-padding of the next layer)
// Requires: M%128==0, K%32==0.
// ---------------------------------------------------------------------------
template<int MODE>
__global__ void __launch_bounds__(256, 1) tgemm(
    const h16* __restrict__ A, long long aPS, int lda, long long aZ,
    const h16* __restrict__ B, long long bPS, int ldb,
    const float* __restrict__ bias,
    float* __restrict__ C, int ldc, long long cZ,
    int Nn, int K, float oscale,
    const float* __restrict__ u, const float* __restrict__ sw,
    h16* __restrict__ Dh, long long dPS, int dldc, int wlim)
{
    extern __shared__ char smem[];
    const uint32_t sb = smem_u32(smem);
    const int tid  = threadIdx.x;
    const int lane = tid & 31, wid = tid >> 5;
    const int wm = wid >> 2, wn = wid & 3;            // 2 x 4 warp grid
    const int bn = blockIdx.x * 128, bm = blockIdx.y * 128;

    A += (long long)blockIdx.z * aZ;
    if (MODE == 2) C += (long long)blockIdx.z * cZ;

    float accM[4][4][4], accC[4][4][4];
#pragma unroll
    for (int i = 0; i < 4; i++)
#pragma unroll
        for (int j = 0; j < 4; j++)
#pragma unroll
            for (int r = 0; r < 4; r++) { accM[i][j][r] = 0.f; accC[i][j][r] = 0.f; }

    const uint32_t aOff = (uint32_t)((wm * 64 + (lane & 15)) * 80 + (lane >> 4) * 16);
    const uint32_t bOff = (uint32_t)((wn * 32 + (lane & 7) + ((lane >> 4) & 1) * 8) * 80
                                     + ((lane >> 3) & 1) * 16);

    const int nch = K >> 5;

    auto load_chunk = [&](int s, int st) {
        const uint32_t base = sb + (uint32_t)st * STAGEB;
#pragma unroll
        for (int it = 0; it < 8; it++) {
            const int v = tid + it * 256;
            const int plane = v >> 9;           // 0,1 = A planes; 2,3 = B planes
            const int rem = v & 511;
            const int row = rem >> 2, seg = rem & 3;
            const uint32_t soff = base + plane * PLANEB + row * 80 + seg * 16;
            if (plane < 2) {
                const h16* g = A + (long long)plane * aPS +
                               (long long)(bm + row) * lda + s * 32 + seg * 8;
                cp16(soff, g, 16);
            } else {
                const int n = bn + row;
                const bool ok = n < Nn;
                const h16* g = B + (long long)(plane - 2) * bPS +
                               (long long)(ok ? n : 0) * ldb + s * 32 + seg * 8;
                cp16(soff, g, ok ? 16u : 0u);
            }
        }
        asm volatile("cp.async.commit_group;");
    };

    if (0 < nch) load_chunk(0, 0); else asm volatile("cp.async.commit_group;");
    if (1 < nch) load_chunk(1, 1); else asm volatile("cp.async.commit_group;");

    for (int s = 0; s < nch; ++s) {
        const int st = s % 3;
        // stage s landed for THIS thread (pending <= 1 group = stage s+1)
        asm volatile("cp.async.wait_group 1;");
        // all threads' stage-s data visible AND all warps done compute(s-1)
        __syncthreads();
        if (s + 2 < nch) load_chunk(s + 2, (s + 2) % 3);   // stage (s-1)%3, now free
        else             asm volatile("cp.async.commit_group;");

        const uint32_t stage = sb + (uint32_t)st * STAGEB;
#pragma unroll
        for (int kk = 0; kk < 2; kk++) {
            const uint32_t ko = kk * 32;          // 16 cols = 32 B
            uint32_t af[4][4], b0r[4][2], b1r[4][2];
#pragma unroll
            for (int i = 0; i < 4; i++)
                ldm4(af[i][0], af[i][1], af[i][2], af[i][3],
                     stage + aOff + ko + i * (16 * 80));
            ldm4(b0r[0][0], b0r[0][1], b0r[1][0], b0r[1][1],
                 stage + 2 * PLANEB + bOff + ko);
            ldm4(b0r[2][0], b0r[2][1], b0r[3][0], b0r[3][1],
                 stage + 2 * PLANEB + bOff + ko + 16 * 80);
            ldm4(b1r[0][0], b1r[0][1], b1r[1][0], b1r[1][1],
                 stage + 3 * PLANEB + bOff + ko);
            ldm4(b1r[2][0], b1r[2][1], b1r[3][0], b1r[3][1],
                 stage + 3 * PLANEB + bOff + ko + 16 * 80);

#pragma unroll
            for (int i = 0; i < 4; i++)
#pragma unroll
                for (int j = 0; j < 4; j++) {
                    mma16816(accM[i][j], af[i], b0r[j]);
                    mma16816(accC[i][j], af[i], b1r[j]);
                }
#pragma unroll
            for (int i = 0; i < 4; i++)
                ldm4(af[i][0], af[i][1], af[i][2], af[i][3],
                     stage + PLANEB + aOff + ko + i * (16 * 80));
#pragma unroll
            for (int i = 0; i < 4; i++)
#pragma unroll
                for (int j = 0; j < 4; j++)
                    mma16816(accC[i][j], af[i], b0r[j]);
        }
    }

    // ---- epilogue ----
    const int gr = lane >> 2, tig = lane & 3;
    if (MODE == 3) {
#pragma unroll
        for (int i = 0; i < 4; i++) {
            const int m1 = bm + wm * 64 + i * 16 + gr;
            const int m2 = m1 + 8;
            const float* u1 = u + (long long)(m1 / NIMG) * DIM;
            const float* u2 = u + (long long)(m2 / NIMG) * DIM;
            float s1 = 0.f, s2 = 0.f;
#pragma unroll
            for (int j = 0; j < 4; j++) {
                const int c = bn + wn * 32 + j * 8 + 2 * tig;
                float w0 = sw[c], w1 = sw[c + 1];
                float v;
                v = (accM[i][j][0] + accC[i][j][0]) * oscale + u1[c];     s1 += fmaxf(v, 0.f) * w0;
                v = (accM[i][j][1] + accC[i][j][1]) * oscale + u1[c + 1]; s1 += fmaxf(v, 0.f) * w1;
                v = (accM[i][j][2] + accC[i][j][2]) * oscale + u2[c];     s2 += fmaxf(v, 0.f) * w0;
                v = (accM[i][j][3] + accC[i][j][3]) * oscale + u2[c + 1]; s2 += fmaxf(v, 0.f) * w1;
            }
            s1 += __shfl_xor_sync(0xffffffffu, s1, 1);
            s1 += __shfl_xor_sync(0xffffffffu, s1, 2);
            s2 += __shfl_xor_sync(0xffffffffu, s2, 1);
            s2 += __shfl_xor_sync(0xffffffffu, s2, 2);
            if (tig == 0) {
                atomicAdd(&g_score[m1], s1);
                atomicAdd(&g_score[m2], s2);
            }
        }
    } else if (MODE == 4 || MODE == 5) {
#pragma unroll
        for (int i = 0; i < 4; i++) {
            const int m1 = bm + wm * 64 + i * 16 + gr;
#pragma unroll
            for (int j = 0; j < 4; j++) {
                const int c = bn + wn * 32 + j * 8 + 2 * tig;
                if (c < wlim) {
                    float v0 = 0.f, v1 = 0.f, v2 = 0.f, v3 = 0.f;
                    if (c < Nn) {
                        const float b0 = bias[c], b1 = bias[c + 1];
                        v0 = (accM[i][j][0] + accC[i][j][0]) * oscale + b0;
                        v1 = (accM[i][j][1] + accC[i][j][1]) * oscale + b1;
                        v2 = (accM[i][j][2] + accC[i][j][2]) * oscale + b0;
                        v3 = (accM[i][j][3] + accC[i][j][3]) * oscale + b1;
                        if (MODE == 4) {
                            v0 = fmaxf(v0, 0.f); v1 = fmaxf(v1, 0.f);
                            v2 = fmaxf(v2, 0.f); v3 = fmaxf(v3, 0.f);
                        }
                    }
                    split_store(Dh, dPS, (long long)m1 * dldc + c, v0, v1);
                    split_store(Dh, dPS, (long long)(m1 + 8) * dldc + c, v2, v3);
                }
            }
        }
    } else {
#pragma unroll
        for (int i = 0; i < 4; i++) {
            const int m1 = bm + wm * 64 + i * 16 + gr;
#pragma unroll
            for (int j = 0; j < 4; j++) {
                const int c = bn + wn * 32 + j * 8 + 2 * tig;
                if (c < Nn) {
                    float b0 = 0.f, b1 = 0.f;
                    if (MODE != 2) { b0 = bias[c]; b1 = bias[c + 1]; }
                    float v0 = (accM[i][j][0] + accC[i][j][0]) * oscale + b0;
                    float v1 = (accM[i][j][1] + accC[i][j][1]) * oscale + b1;
                    float v2 = (accM[i][j][2] + accC[i][j][2]) * oscale + b0;
                    float v3 = (accM[i][j][3] + accC[i][j][3]) * oscale + b1;
                    *(float2*)&C[(long long)m1 * ldc + c]       = make_float2(v0, v1);
                    *(float2*)&C[(long long)(m1 + 8) * ldc + c] = make_float2(v2, v3);
                }
            }
        }
    }
}

// ---------------------------------------------------------------------------
__global__ void split2(const float* __restrict__ src, h16* __restrict__ dst,
                       long long ps, long long total, int srcCols, int dstCols,
                       float preScale)
{
    long long idx = (long long)blockIdx.x * blockDim.x + threadIdx.x;
    if (idx >= total) return;
    float x;
    if (srcCols == dstCols) x = src[idx];
    else {
        long long r = idx / dstCols;
        int k = (int)(idx - r * dstCols);
        x = (k < srcCols) ? src[r * srcCols + k] : 0.f;
    }
    x *= preScale;
    h16 h0 = __float2half_rn(x);
    h16 h1 = __float2half_rn(x - __half2float(h0));
    dst[idx] = h0; dst[ps + idx] = h1;
}

__global__ void split2T(const float* __restrict__ src, h16* __restrict__ dst,
                        long long ps, int N, int K, int Kpad, float preScale)
{
    int idx = blockIdx.x * blockDim.x + threadIdx.x;
    if (idx >= N * Kpad) return;
    int n = idx / Kpad, k = idx % Kpad;
    float x = (k < K) ? src[(long long)k * N + n] * preScale : 0.f;
    h16 h0 = __float2half_rn(x);
    h16 h1 = __float2half_rn(x - __half2float(h0));
    dst[idx] = h0; dst[ps + idx] = h1;
}

// max over T windows + bias + relu, then split directly into g_ca planes
__global__ void conv_reduce_split(const float* __restrict__ bias, int T, int coff)
{
    int idx = blockIdx.x * blockDim.x + threadIdx.x;
    if (idx >= BATCH * 200) return;
    int c = idx % 200, n = idx / 200;
    float v = g_tmp[idx];
    for (int t = 1; t < T; t++) v = fmaxf(v, g_tmp[(size_t)t * TS + idx]);
    v = fmaxf(v + bias[c], 0.f);
    h16 h0 = __float2half_rn(v);
    h16 h1 = __float2half_rn(v - __half2float(h0));
    long long o = (long long)n * 640 + coff + c;
    g_ca[o] = h0; g_ca[CPS + o] = h1;
}

__global__ void zero_score()
{
    int i = blockIdx.x * blockDim.x + threadIdx.x;
    if (i < M5) g_score[i] = 0.f;
}

__global__ void finalize_f32(const float* __restrict__ fcs_b, float* __restrict__ out)
{
    int n = blockIdx.x * blockDim.x + threadIdx.x;
    if (n >= BATCH) return;
    float fb = fcs_b[0];
    float s[5];
#pragma unroll
    for (int i = 0; i < 5; i++) s[i] = g_score[n * 5 + i] + fb;
#pragma unroll
    for (int i = 0; i < 5; i++) {
        int si = n * 5 + i;
        out[si] = s[i];
        int r = 0;
#pragma unroll
        for (int j = 0; j < 5; j++)
            r += (s[j] > s[i]) || ((s[j] == s[i]) && (j < i));
        out[M5 + si] = (float)r;
    }
}

extern "C" void kernel_launch(void* const* d_in, const int* in_sizes, int n_in,
                              void* d_out, int out_size)
{
    const float* feats = (const float*)d_in[0];
    const float* w2    = (const float*)d_in[1];
    const float* b2    = (const float*)d_in[2];
    const float* w3    = (const float*)d_in[3];
    const float* b3    = (const float*)d_in[4];
    const float* w5    = (const float*)d_in[5];
    const float* b5    = (const float*)d_in[6];
    const float* fc1_w = (const float*)d_in[7];
    const float* fc1_b = (const float*)d_in[8];
    const float* fc2_w = (const float*)d_in[9];
    const float* fc2_b = (const float*)d_in[10];
    const float* fc0_w = (const float*)d_in[11];
    const float* fc0_b = (const float*)d_in[12];
    const float* fcs_w = (const float*)d_in[13];
    const float* fcs_b = (const float*)d_in[14];

    float *pt, *pu;
    cudaGetSymbolAddress((void**)&pt,  g_tmp);
    cudaGetSymbolAddress((void**)&pu,  g_u);
    h16 *fa, *ca, *ha, *cia, *w2a, *w3a, *w5a, *f1a, *f2a, *f0aa, *f0ua;
    cudaGetSymbolAddress((void**)&fa,   g_fa);
    cudaGetSymbolAddress((void**)&ca,   g_ca);
    cudaGetSymbolAddress((void**)&ha,   g_ha);
    cudaGetSymbolAddress((void**)&cia,  g_cia);
    cudaGetSymbolAddress((void**)&w2a,  g_w2a);
    cudaGetSymbolAddress((void**)&w3a,  g_w3a);
    cudaGetSymbolAddress((void**)&w5a,  g_w5a);
    cudaGetSymbolAddress((void**)&f1a,  g_f1a);
    cudaGetSymbolAddress((void**)&f2a,  g_f2a);
    cudaGetSymbolAddress((void**)&f0aa, g_f0aa);
    cudaGetSymbolAddress((void**)&f0ua, g_f0ua);

    cudaFuncSetAttribute(tgemm<0>, cudaFuncAttributeMaxDynamicSharedMemorySize, SMT);
    cudaFuncSetAttribute(tgemm<2>, cudaFuncAttributeMaxDynamicSharedMemorySize, SMT);
    cudaFuncSetAttribute(tgemm<3>, cudaFuncAttributeMaxDynamicSharedMemorySize, SMT);
    cudaFuncSetAttribute(tgemm<4>, cudaFuncAttributeMaxDynamicSharedMemorySize, SMT);
    cudaFuncSetAttribute(tgemm<5>, cudaFuncAttributeMaxDynamicSharedMemorySize, SMT);

    dim3 blk(256);
    const int MB = BATCH / 128;

    // ---- splits (feats + weights only; intermediates are split in-epilogue) ----
    split2<<<(int)((83886080LL + 255) / 256), blk>>>(feats, fa, FPS, 83886080LL,
                                                     2560, 2560, 1.f);
    split2<<<(204800 + 255) / 256, blk>>>(w2, w2a, 200 * 1024, 204800, 1024, 1024, WSCALE);
    split2<<<(307200 + 255) / 256, blk>>>(w3, w3a, 200 * 1536, 307200, 1536, 1536, WSCALE);
    split2<<<(512000 + 255) / 256, blk>>>(w5, w5a, 200 * 2560, 512000, 2560, 2560, WSCALE);
    split2T<<<(600 * 640 + 255) / 256, blk>>>(fc1_w, f1a, 600 * 640, 600, 600, 640, WSCALE);
    split2T<<<(512 * 640 + 255) / 256, blk>>>(fc2_w, f2a, 512 * 640, 512, 600, 640, WSCALE);
    split2T<<<(512 * 512 + 255) / 256, blk>>>(fc0_w, f0aa, 512 * 512, 512, 512, 512, WSCALE);
    split2T<<<(512 * 512 + 255) / 256, blk>>>(fc0_w + (size_t)DIM * DIM, f0ua,
                                              512 * 512, 512, 512, 512, WSCALE);

    // ---- conv blocks ----
    tgemm<2><<<dim3(2, MB, 4), blk, SMT>>>(fa, FPS, 2560, 512,
        w2a, 200 * 1024, 1024, nullptr, pt, 200, TS, 200, 1024, IWSCALE,
        nullptr, nullptr, nullptr, 0, 0, 0);
    conv_reduce_split<<<(BATCH * 200 + 255) / 256, blk>>>(b2, 4, 0);

    tgemm<2><<<dim3(2, MB, 3), blk, SMT>>>(fa, FPS, 2560, 512,
        w3a, 200 * 1536, 1536, nullptr, pt, 200, TS, 200, 1536, IWSCALE,
        nullptr, nullptr, nullptr, 0, 0, 0);
    conv_reduce_split<<<(BATCH * 200 + 255) / 256, blk>>>(b3, 3, 200);

    // conv5: relu+bias -> split planes of g_ca at col offset 400
    // (dst cols 400..639; c in [200,240) zero-fills g_ca cols 600..639)
    tgemm<4><<<dim3(2, MB, 1), blk, SMT>>>(fa, FPS, 2560, 0,
        w5a, 200 * 2560, 2560, b5, nullptr, 0, 0, 200, 2560, IWSCALE,
        nullptr, nullptr, ca + 400, CPS, 640, 240);

    // fc1: relu+bias -> g_ha planes (cols 600..639 zero-filled)
    tgemm<4><<<dim3(5, MB, 1), blk, SMT>>>(ca, CPS, 640, 0,
        f1a, 600 * 640, 640, fc1_b, nullptr, 0, 0, 600, 640, IWSCALE,
        nullptr, nullptr, ha, CPS, 640, 640);

    // fc2: bias -> g_cia planes
    tgemm<5><<<dim3(4, MB, 1), blk, SMT>>>(ha, CPS, 640, 0,
        f2a, 512 * 640, 640, fc2_b, nullptr, 0, 0, 512, 640, IWSCALE,
        nullptr, nullptr, cia, CIPS, 512, 512);

    // u = ci @ fc0_w[512:] + fc0_b (fp32, read by score epilogue)
    tgemm<0><<<dim3(4, MB, 1), blk, SMT>>>(cia, CIPS, 512, 0,
        f0ua, 512 * 512, 512, fc0_b, pu, DIM, 0, 512, 512, IWSCALE,
        nullptr, nullptr, nullptr, 0, 0, 0);

    // ---- fused score GEMM ----
    zero_score<<<(M5 + 255) / 256, blk>>>();
    tgemm<3><<<dim3(4, M5 / 128, 1), blk, SMT>>>(fa, FPS, 512, 0,
        f0aa, 512 * 512, 512, nullptr, nullptr, 0, 0, 512, 512, IWSCALE,
        pu, fcs_w, nullptr, 0, 0, 0);

    finalize_f32<<<(BATCH + 255) / 256, blk>>>(fcs_b, (float*)d_out);
}

// round 15
// speedup vs baseline: 2.2061x; 1.0704x over previous
#include <cuda_runtime.h>
#include <cuda_fp16.h>
#include <cstdint>

typedef __half h16;

#define BATCH 32768
#define NIMG  5
#define DIM   512
#define DCAT  600
#define M5    (BATCH * NIMG)
#define TS    (BATCH * 200)

#define WSCALE   128.0f
#define IWSCALE  (1.0f / 128.0f)

// ---- fp32 scratch ----
__device__ __align__(128) float g_tmp[4 * TS];
__device__ __align__(128) float g_u[BATCH * DIM];
__device__ __align__(128) float g_score[M5];

// ---- fp16 split planes (x = h0 + h1, ~24-bit total) ----
#define FPS  ((long long)BATCH * 2560)
#define CPS  ((long long)BATCH * 640)
#define CIPS ((long long)BATCH * 512)
__device__ __align__(128) h16 g_fa [2 * FPS];
__device__ __align__(128) h16 g_ca [2 * CPS];     // conv concat, 640-wide
__device__ __align__(128) h16 g_ha [2 * CPS];     // relu(fc1), 640-wide
__device__ __align__(128) h16 g_cia[2 * CIPS];    // fc2 out, 512-wide
__device__ __align__(128) h16 g_w2a[2 * 200 * 1024];
__device__ __align__(128) h16 g_w3a[2 * 200 * 1536];
__device__ __align__(128) h16 g_w5a[2 * 200 * 2560];
__device__ __align__(128) h16 g_f1a[2 * 600 * 640];
__device__ __align__(128) h16 g_f2a[2 * 512 * 640];
__device__ __align__(128) h16 g_f0aa[2 * 512 * 512];
__device__ __align__(128) h16 g_f0ua[2 * 512 * 512];

// ---- portable PTX helpers (sm_80+ ISA only) ----
__device__ __forceinline__ uint32_t smem_u32(const void* p) {
    uint32_t a;
    asm("{ .reg .u64 t; cvta.to.shared.u64 t, %1; cvt.u32.u64 %0, t; }"
        : "=r"(a) : "l"(p));
    return a;
}
__device__ __forceinline__ void cp16(uint32_t saddr, const void* gaddr, uint32_t srcsz) {
    asm volatile("cp.async.cg.shared.global [%0], [%1], 16, %2;"
                 :: "r"(saddr), "l"(gaddr), "r"(srcsz));
}
__device__ __forceinline__ void ldm4(uint32_t& r0, uint32_t& r1, uint32_t& r2,
                                     uint32_t& r3, uint32_t addr) {
    asm volatile("ldmatrix.sync.aligned.m8n8.x4.shared.b16 {%0,%1,%2,%3}, [%4];"
                 : "=r"(r0), "=r"(r1), "=r"(r2), "=r"(r3) : "r"(addr));
}
__device__ __forceinline__ void mma16816(float* d, const uint32_t* a,
                                         const uint32_t* b) {
    asm volatile(
        "mma.sync.aligned.m16n8k16.row.col.f32.f16.f16.f32 "
        "{%0,%1,%2,%3}, {%4,%5,%6,%7}, {%8,%9}, {%0,%1,%2,%3};"
        : "+f"(d[0]), "+f"(d[1]), "+f"(d[2]), "+f"(d[3])
        : "r"(a[0]), "r"(a[1]), "r"(a[2]), "r"(a[3]), "r"(b[0]), "r"(b[1]));
}
__device__ __forceinline__ void split_store(h16* dst, long long dPS,
                                            long long idx, float v0, float v1) {
    h16 a0 = __float2half_rn(v0);
    h16 b0 = __float2half_rn(v1);
    h16 a1 = __float2half_rn(v0 - __half2float(a0));
    h16 b1 = __float2half_rn(v1 - __half2float(b0));
    *(__half2*)&dst[idx]       = __halves2half2(a0, b0);
    *(__half2*)&dst[dPS + idx] = __halves2half2(a1, b1);
}

// smem: 3-stage ring; per stage 2 A planes (128 rows) + 2 B planes (64 rows),
// k32 chunks, rows 64B data padded to 80B.
#define PLANEA 10240           // 128 * 80
#define PLANEBB 5120           // 64 * 80
#define STAGEB (2 * PLANEA + 2 * PLANEBB)   // 30720
#define SMT    (3 * STAGEB)                  // 92160 B  -> 2 CTAs/SM

// ---------------------------------------------------------------------------
// Tensor-core GEMM, fp16x2 split, dual accumulators. Block tile 128x64,
// 8 warps in 4x2, warp tile 32x32 -> 2 CTAs/SM.
//   GRID: blockIdx.x = N-block(64), blockIdx.y = M-block(128), z = conv window.
//   MODE 0:+bias->f32  2:raw->f32(+z C offset)  3:fused score
//   MODE 4:+bias,relu->split planes  5:+bias->split planes
// Requires: M%128==0, K%32==0.
// ---------------------------------------------------------------------------
template<int MODE>
__global__ void __launch_bounds__(256, 2) tgemm(
    const h16* __restrict__ A, long long aPS, int lda, long long aZ,
    const h16* __restrict__ B, long long bPS, int ldb,
    const float* __restrict__ bias,
    float* __restrict__ C, int ldc, long long cZ,
    int Nn, int K, float oscale,
    const float* __restrict__ u, const float* __restrict__ sw,
    h16* __restrict__ Dh, long long dPS, int dldc, int wlim)
{
    extern __shared__ char smem[];
    const uint32_t sb = smem_u32(smem);
    const int tid  = threadIdx.x;
    const int lane = tid & 31, wid = tid >> 5;
    const int wm = wid >> 1, wn = wid & 1;            // 4 x 2 warp grid
    const int bn = blockIdx.x * 64, bm = blockIdx.y * 128;

    A += (long long)blockIdx.z * aZ;
    if (MODE == 2) C += (long long)blockIdx.z * cZ;

    float accM[2][4][4], accC[2][4][4];
#pragma unroll
    for (int i = 0; i < 2; i++)
#pragma unroll
        for (int j = 0; j < 4; j++)
#pragma unroll
            for (int r = 0; r < 4; r++) { accM[i][j][r] = 0.f; accC[i][j][r] = 0.f; }

    const uint32_t aOff = (uint32_t)((wm * 32 + (lane & 15)) * 80 + (lane >> 4) * 16);
    const uint32_t bOff = (uint32_t)((wn * 32 + (lane & 7) + ((lane >> 4) & 1) * 8) * 80
                                     + ((lane >> 3) & 1) * 16);

    const int nch = K >> 5;

    // loader: 1536 16B-vectors per stage (A: 2x128x4, B: 2x64x4), 6/thread
    auto load_chunk = [&](int s, int st) {
        const uint32_t base = sb + (uint32_t)st * STAGEB;
#pragma unroll
        for (int it = 0; it < 6; it++) {
            const int v = tid + it * 256;
            if (v < 1024) {                      // A planes
                const int plane = v >> 9;
                const int rem = v & 511;
                const int row = rem >> 2, seg = rem & 3;
                const h16* g = A + (long long)plane * aPS +
                               (long long)(bm + row) * lda + s * 32 + seg * 8;
                cp16(base + plane * PLANEA + row * 80 + seg * 16, g, 16);
            } else {                             // B planes (64 rows)
                const int w = v - 1024;
                const int plane = w >> 8;
                const int rem = w & 255;
                const int row = rem >> 2, seg = rem & 3;
                const int n = bn + row;
                const bool ok = n < Nn;
                const h16* g = B + (long long)plane * bPS +
                               (long long)(ok ? n : 0) * ldb + s * 32 + seg * 8;
                cp16(base + 2 * PLANEA + plane * PLANEBB + row * 80 + seg * 16,
                     g, ok ? 16u : 0u);
            }
        }
        asm volatile("cp.async.commit_group;");
    };

    if (0 < nch) load_chunk(0, 0); else asm volatile("cp.async.commit_group;");
    if (1 < nch) load_chunk(1, 1); else asm volatile("cp.async.commit_group;");

    for (int s = 0; s < nch; ++s) {
        const int st = s % 3;
        asm volatile("cp.async.wait_group 1;");
        __syncthreads();
        if (s + 2 < nch) load_chunk(s + 2, (s + 2) % 3);
        else             asm volatile("cp.async.commit_group;");

        const uint32_t stage = sb + (uint32_t)st * STAGEB;
        const uint32_t bbase = stage + 2 * PLANEA;
#pragma unroll
        for (int kk = 0; kk < 2; kk++) {
            const uint32_t ko = kk * 32;          // 16 cols = 32 B
            uint32_t af[2][4], b0r[4][2], b1r[4][2];
#pragma unroll
            for (int i = 0; i < 2; i++)
                ldm4(af[i][0], af[i][1], af[i][2], af[i][3],
                     stage + aOff + ko + i * (16 * 80));
            ldm4(b0r[0][0], b0r[0][1], b0r[1][0], b0r[1][1], bbase + bOff + ko);
            ldm4(b0r[2][0], b0r[2][1], b0r[3][0], b0r[3][1],
                 bbase + bOff + ko + 16 * 80);
            ldm4(b1r[0][0], b1r[0][1], b1r[1][0], b1r[1][1],
                 bbase + PLANEBB + bOff + ko);
            ldm4(b1r[2][0], b1r[2][1], b1r[3][0], b1r[3][1],
                 bbase + PLANEBB + bOff + ko + 16 * 80);

#pragma unroll
            for (int i = 0; i < 2; i++)
#pragma unroll
                for (int j = 0; j < 4; j++) {
                    mma16816(accM[i][j], af[i], b0r[j]);
                    mma16816(accC[i][j], af[i], b1r[j]);
                }
#pragma unroll
            for (int i = 0; i < 2; i++)
                ldm4(af[i][0], af[i][1], af[i][2], af[i][3],
                     stage + PLANEA + aOff + ko + i * (16 * 80));
#pragma unroll
            for (int i = 0; i < 2; i++)
#pragma unroll
                for (int j = 0; j < 4; j++)
                    mma16816(accC[i][j], af[i], b0r[j]);
        }
    }

    // ---- epilogue ----
    const int gr = lane >> 2, tig = lane & 3;
    if (MODE == 3) {
#pragma unroll
        for (int i = 0; i < 2; i++) {
            const int m1 = bm + wm * 32 + i * 16 + gr;
            const int m2 = m1 + 8;
            const float* u1 = u + (long long)(m1 / NIMG) * DIM;
            const float* u2 = u + (long long)(m2 / NIMG) * DIM;
            float s1 = 0.f, s2 = 0.f;
#pragma unroll
            for (int j = 0; j < 4; j++) {
                const int c = bn + wn * 32 + j * 8 + 2 * tig;
                float w0 = sw[c], w1 = sw[c + 1];
                float v;
                v = (accM[i][j][0] + accC[i][j][0]) * oscale + u1[c];     s1 += fmaxf(v, 0.f) * w0;
                v = (accM[i][j][1] + accC[i][j][1]) * oscale + u1[c + 1]; s1 += fmaxf(v, 0.f) * w1;
                v = (accM[i][j][2] + accC[i][j][2]) * oscale + u2[c];     s2 += fmaxf(v, 0.f) * w0;
                v = (accM[i][j][3] + accC[i][j][3]) * oscale + u2[c + 1]; s2 += fmaxf(v, 0.f) * w1;
            }
            s1 += __shfl_xor_sync(0xffffffffu, s1, 1);
            s1 += __shfl_xor_sync(0xffffffffu, s1, 2);
            s2 += __shfl_xor_sync(0xffffffffu, s2, 1);
            s2 += __shfl_xor_sync(0xffffffffu, s2, 2);
            if (tig == 0) {
                atomicAdd(&g_score[m1], s1);
                atomicAdd(&g_score[m2], s2);
            }
        }
    } else if (MODE == 4 || MODE == 5) {
#pragma unroll
        for (int i = 0; i < 2; i++) {
            const int m1 = bm + wm * 32 + i * 16 + gr;
#pragma unroll
            for (int j = 0; j < 4; j++) {
                const int c = bn + wn * 32 + j * 8 + 2 * tig;
                if (c < wlim) {
                    float v0 = 0.f, v1 = 0.f, v2 = 0.f, v3 = 0.f;
                    if (c < Nn) {
                        const float b0 = bias[c], b1 = bias[c + 1];
                        v0 = (accM[i][j][0] + accC[i][j][0]) * oscale + b0;
                        v1 = (accM[i][j][1] + accC[i][j][1]) * oscale + b1;
                        v2 = (accM[i][j][2] + accC[i][j][2]) * oscale + b0;
                        v3 = (accM[i][j][3] + accC[i][j][3]) * oscale + b1;
                        if (MODE == 4) {
                            v0 = fmaxf(v0, 0.f); v1 = fmaxf(v1, 0.f);
                            v2 = fmaxf(v2, 0.f); v3 = fmaxf(v3, 0.f);
                        }
                    }
                    split_store(Dh, dPS, (long long)m1 * dldc + c, v0, v1);
                    split_store(Dh, dPS, (long long)(m1 + 8) * dldc + c, v2, v3);
                }
            }
        }
    } else {
#pragma unroll
        for (int i = 0; i < 2; i++) {
            const int m1 = bm + wm * 32 + i * 16 + gr;
#pragma unroll
            for (int j = 0; j < 4; j++) {
                const int c = bn + wn * 32 + j * 8 + 2 * tig;
                if (c < Nn) {
                    float b0 = 0.f, b1 = 0.f;
                    if (MODE != 2) { b0 = bias[c]; b1 = bias[c + 1]; }
                    float v0 = (accM[i][j][0] + accC[i][j][0]) * oscale + b0;
                    float v1 = (accM[i][j][1] + accC[i][j][1]) * oscale + b1;
                    float v2 = (accM[i][j][2] + accC[i][j][2]) * oscale + b0;
                    float v3 = (accM[i][j][3] + accC[i][j][3]) * oscale + b1;
                    *(float2*)&C[(long long)m1 * ldc + c]       = make_float2(v0, v1);
                    *(float2*)&C[(long long)(m1 + 8) * ldc + c] = make_float2(v2, v3);
                }
            }
        }
    }
}

// ---------------------------------------------------------------------------
__global__ void split2(const float* __restrict__ src, h16* __restrict__ dst,
                       long long ps, long long total, int srcCols, int dstCols,
                       float preScale)
{
    long long idx = (long long)blockIdx.x * blockDim.x + threadIdx.x;
    if (idx >= total) return;
    float x;
    if (srcCols == dstCols) x = src[idx];
    else {
        long long r = idx / dstCols;
        int k = (int)(idx - r * dstCols);
        x = (k < srcCols) ? src[r * srcCols + k] : 0.f;
    }
    x *= preScale;
    h16 h0 = __float2half_rn(x);
    h16 h1 = __float2half_rn(x - __half2float(h0));
    dst[idx] = h0; dst[ps + idx] = h1;
}

__global__ void split2T(const float* __restrict__ src, h16* __restrict__ dst,
                        long long ps, int N, int K, int Kpad, float preScale)
{
    int idx = blockIdx.x * blockDim.x + threadIdx.x;
    if (idx >= N * Kpad) return;
    int n = idx / Kpad, k = idx % Kpad;
    float x = (k < K) ? src[(long long)k * N + n] * preScale : 0.f;
    h16 h0 = __float2half_rn(x);
    h16 h1 = __float2half_rn(x - __half2float(h0));
    dst[idx] = h0; dst[ps + idx] = h1;
}

__global__ void conv_reduce_split(const float* __restrict__ bias, int T, int coff)
{
    int idx = blockIdx.x * blockDim.x + threadIdx.x;
    if (idx >= BATCH * 200) return;
    int c = idx % 200, n = idx / 200;
    float v = g_tmp[idx];
    for (int t = 1; t < T; t++) v = fmaxf(v, g_tmp[(size_t)t * TS + idx]);
    v = fmaxf(v + bias[c], 0.f);
    h16 h0 = __float2half_rn(v);
    h16 h1 = __float2half_rn(v - __half2float(h0));
    long long o = (long long)n * 640 + coff + c;
    g_ca[o] = h0; g_ca[CPS + o] = h1;
}

__global__ void zero_score()
{
    int i = blockIdx.x * blockDim.x + threadIdx.x;
    if (i < M5) g_score[i] = 0.f;
}

__global__ void finalize_f32(const float* __restrict__ fcs_b, float* __restrict__ out)
{
    int n = blockIdx.x * blockDim.x + threadIdx.x;
    if (n >= BATCH) return;
    float fb = fcs_b[0];
    float s[5];
#pragma unroll
    for (int i = 0; i < 5; i++) s[i] = g_score[n * 5 + i] + fb;
#pragma unroll
    for (int i = 0; i < 5; i++) {
        int si = n * 5 + i;
        out[si] = s[i];
        int r = 0;
#pragma unroll
        for (int j = 0; j < 5; j++)
            r += (s[j] > s[i]) || ((s[j] == s[i]) && (j < i));
        out[M5 + si] = (float)r;
    }
}

extern "C" void kernel_launch(void* const* d_in, const int* in_sizes, int n_in,
                              void* d_out, int out_size)
{
    const float* feats = (const float*)d_in[0];
    const float* w2    = (const float*)d_in[1];
    const float* b2    = (const float*)d_in[2];
    const float* w3    = (const float*)d_in[3];
    const float* b3    = (const float*)d_in[4];
    const float* w5    = (const float*)d_in[5];
    const float* b5    = (const float*)d_in[6];
    const float* fc1_w = (const float*)d_in[7];
    const float* fc1_b = (const float*)d_in[8];
    const float* fc2_w = (const float*)d_in[9];
    const float* fc2_b = (const float*)d_in[10];
    const float* fc0_w = (const float*)d_in[11];
    const float* fc0_b = (const float*)d_in[12];
    const float* fcs_w = (const float*)d_in[13];
    const float* fcs_b = (const float*)d_in[14];

    float *pt, *pu;
    cudaGetSymbolAddress((void**)&pt,  g_tmp);
    cudaGetSymbolAddress((void**)&pu,  g_u);
    h16 *fa, *ca, *ha, *cia, *w2a, *w3a, *w5a, *f1a, *f2a, *f0aa, *f0ua;
    cudaGetSymbolAddress((void**)&fa,   g_fa);
    cudaGetSymbolAddress((void**)&ca,   g_ca);
    cudaGetSymbolAddress((void**)&ha,   g_ha);
    cudaGetSymbolAddress((void**)&cia,  g_cia);
    cudaGetSymbolAddress((void**)&w2a,  g_w2a);
    cudaGetSymbolAddress((void**)&w3a,  g_w3a);
    cudaGetSymbolAddress((void**)&w5a,  g_w5a);
    cudaGetSymbolAddress((void**)&f1a,  g_f1a);
    cudaGetSymbolAddress((void**)&f2a,  g_f2a);
    cudaGetSymbolAddress((void**)&f0aa, g_f0aa);
    cudaGetSymbolAddress((void**)&f0ua, g_f0ua);

    cudaFuncSetAttribute(tgemm<0>, cudaFuncAttributeMaxDynamicSharedMemorySize, SMT);
    cudaFuncSetAttribute(tgemm<2>, cudaFuncAttributeMaxDynamicSharedMemorySize, SMT);
    cudaFuncSetAttribute(tgemm<3>, cudaFuncAttributeMaxDynamicSharedMemorySize, SMT);
    cudaFuncSetAttribute(tgemm<4>, cudaFuncAttributeMaxDynamicSharedMemorySize, SMT);
    cudaFuncSetAttribute(tgemm<5>, cudaFuncAttributeMaxDynamicSharedMemorySize, SMT);

    dim3 blk(256);
    const int MB = BATCH / 128;

    // ---- splits (feats + weights only) ----
    split2<<<(int)((83886080LL + 255) / 256), blk>>>(feats, fa, FPS, 83886080LL,
                                                     2560, 2560, 1.f);
    split2<<<(204800 + 255) / 256, blk>>>(w2, w2a, 200 * 1024, 204800, 1024, 1024, WSCALE);
    split2<<<(307200 + 255) / 256, blk>>>(w3, w3a, 200 * 1536, 307200, 1536, 1536, WSCALE);
    split2<<<(512000 + 255) / 256, blk>>>(w5, w5a, 200 * 2560, 512000, 2560, 2560, WSCALE);
    split2T<<<(600 * 640 + 255) / 256, blk>>>(fc1_w, f1a, 600 * 640, 600, 600, 640, WSCALE);
    split2T<<<(512 * 640 + 255) / 256, blk>>>(fc2_w, f2a, 512 * 640, 512, 600, 640, WSCALE);
    split2T<<<(512 * 512 + 255) / 256, blk>>>(fc0_w, f0aa, 512 * 512, 512, 512, 512, WSCALE);
    split2T<<<(512 * 512 + 255) / 256, blk>>>(fc0_w + (size_t)DIM * DIM, f0ua,
                                              512 * 512, 512, 512, 512, WSCALE);

    // ---- conv blocks (grid.x = N/64) ----
    tgemm<2><<<dim3(4, MB, 4), blk, SMT>>>(fa, FPS, 2560, 512,
        w2a, 200 * 1024, 1024, nullptr, pt, 200, TS, 200, 1024, IWSCALE,
        nullptr, nullptr, nullptr, 0, 0, 0);
    conv_reduce_split<<<(BATCH * 200 + 255) / 256, blk>>>(b2, 4, 0);

    tgemm<2><<<dim3(4, MB, 3), blk, SMT>>>(fa, FPS, 2560, 512,
        w3a, 200 * 1536, 1536, nullptr, pt, 200, TS, 200, 1536, IWSCALE,
        nullptr, nullptr, nullptr, 0, 0, 0);
    conv_reduce_split<<<(BATCH * 200 + 255) / 256, blk>>>(b3, 3, 200);

    // conv5: relu+bias -> split planes of g_ca at col offset 400
    tgemm<4><<<dim3(4, MB, 1), blk, SMT>>>(fa, FPS, 2560, 0,
        w5a, 200 * 2560, 2560, b5, nullptr, 0, 0, 200, 2560, IWSCALE,
        nullptr, nullptr, ca + 400, CPS, 640, 240);

    // fc1: relu+bias -> g_ha planes (cols 600..639 zero-filled)
    tgemm<4><<<dim3(10, MB, 1), blk, SMT>>>(ca, CPS, 640, 0,
        f1a, 600 * 640, 640, fc1_b, nullptr, 0, 0, 600, 640, IWSCALE,
        nullptr, nullptr, ha, CPS, 640, 640);

    // fc2: bias -> g_cia planes
    tgemm<5><<<dim3(8, MB, 1), blk, SMT>>>(ha, CPS, 640, 0,
        f2a, 512 * 640, 640, fc2_b, nullptr, 0, 0, 512, 640, IWSCALE,
        nullptr, nullptr, cia, CIPS, 512, 512);

    // u = ci @ fc0_w[512:] + fc0_b
    tgemm<0><<<dim3(8, MB, 1), blk, SMT>>>(cia, CIPS, 512, 0,
        f0ua, 512 * 512, 512, fc0_b, pu, DIM, 0, 512, 512, IWSCALE,
        nullptr, nullptr, nullptr, 0, 0, 0);

    // ---- fused score GEMM ----
    zero_score<<<(M5 + 255) / 256, blk>>>();
    tgemm<3><<<dim3(8, M5 / 128, 1), blk, SMT>>>(fa, FPS, 512, 0,
        f0aa, 512 * 512, 512, nullptr, nullptr, 0, 0, 512, 512, IWSCALE,
        pu, fcs_w, nullptr, 0, 0, 0);

    finalize_f32<<<(BATCH + 255) / 256, blk>>>(fcs_b, (float*)d_out);
}

// round 16
// speedup vs baseline: 2.4688x; 1.1191x over previous
#include <cuda_runtime.h>
#include <cuda_fp16.h>
#include <cstdint>

typedef __half h16;

#define BATCH 32768
#define NIMG  5
#define DIM   512
#define DCAT  600
#define M5    (BATCH * NIMG)
#define TS    (BATCH * 200)

#define WSCALE   128.0f
#define IWSCALE  (1.0f / 128.0f)

// ---- fp32 scratch ----
__device__ __align__(128) float g_tmp[4 * TS];
__device__ __align__(128) float g_u[BATCH * DIM];
__device__ __align__(128) float g_score[M5];

// ---- fp16 split planes (x = h0 + h1, ~24-bit total) ----
#define FPS  ((long long)BATCH * 2560)
#define CPS  ((long long)BATCH * 640)
#define CIPS ((long long)BATCH * 512)
__device__ __align__(128) h16 g_fa [2 * FPS];
__device__ __align__(128) h16 g_ca [2 * CPS];     // conv concat, 640-wide
__device__ __align__(128) h16 g_ha [2 * CPS];     // relu(fc1), 640-wide
__device__ __align__(128) h16 g_cia[2 * CIPS];    // fc2 out, 512-wide
__device__ __align__(128) h16 g_w2a[2 * 200 * 1024];
__device__ __align__(128) h16 g_w3a[2 * 200 * 1536];
__device__ __align__(128) h16 g_w5a[2 * 200 * 2560];
__device__ __align__(128) h16 g_f1a[2 * 600 * 640];
__device__ __align__(128) h16 g_f2a[2 * 512 * 640];
__device__ __align__(128) h16 g_f0aa[2 * 512 * 512];
__device__ __align__(128) h16 g_f0ua[2 * 512 * 512];

// ---- portable PTX helpers (sm_80+ ISA only) ----
__device__ __forceinline__ uint32_t smem_u32(const void* p) {
    uint32_t a;
    asm("{ .reg .u64 t; cvta.to.shared.u64 t, %1; cvt.u32.u64 %0, t; }"
        : "=r"(a) : "l"(p));
    return a;
}
__device__ __forceinline__ void cp16(uint32_t saddr, const void* gaddr, uint32_t srcsz) {
    asm volatile("cp.async.cg.shared.global [%0], [%1], 16, %2;"
                 :: "r"(saddr), "l"(gaddr), "r"(srcsz));
}
__device__ __forceinline__ void ldm4(uint32_t& r0, uint32_t& r1, uint32_t& r2,
                                     uint32_t& r3, uint32_t addr) {
    asm volatile("ldmatrix.sync.aligned.m8n8.x4.shared.b16 {%0,%1,%2,%3}, [%4];"
                 : "=r"(r0), "=r"(r1), "=r"(r2), "=r"(r3) : "r"(addr));
}
__device__ __forceinline__ void mma16816(float* d, const uint32_t* a,
                                         const uint32_t* b) {
    asm volatile(
        "mma.sync.aligned.m16n8k16.row.col.f32.f16.f16.f32 "
        "{%0,%1,%2,%3}, {%4,%5,%6,%7}, {%8,%9}, {%0,%1,%2,%3};"
        : "+f"(d[0]), "+f"(d[1]), "+f"(d[2]), "+f"(d[3])
        : "r"(a[0]), "r"(a[1]), "r"(a[2]), "r"(a[3]), "r"(b[0]), "r"(b[1]));
}
__device__ __forceinline__ void split_store(h16* dst, long long dPS,
                                            long long idx, float v0, float v1) {
    h16 a0 = __float2half_rn(v0);
    h16 b0 = __float2half_rn(v1);
    h16 a1 = __float2half_rn(v0 - __half2float(a0));
    h16 b1 = __float2half_rn(v1 - __half2float(b0));
    *(__half2*)&dst[idx]       = __halves2half2(a0, b0);
    *(__half2*)&dst[dPS + idx] = __halves2half2(a1, b1);
}

// smem: 2-stage ring; per stage 2 A planes (128 rows) + 2 B planes (64 rows),
// k64 chunks: rows 128B data padded to 144B (conflict-free ldmatrix).
#define PLANEA 18432           // 128 * 144
#define PLANEBB 9216           // 64 * 144
#define STAGEB (2 * PLANEA + 2 * PLANEBB)   // 55296
#define SMT    (2 * STAGEB)                  // 110592 B -> 2 CTAs/SM

// ---------------------------------------------------------------------------
// Tensor-core GEMM, fp16x2 split, dual accumulators. Block tile 128x64,
// 8 warps in 4x2, warp tile 32x32, K chunks of 64, double-buffered.
//   GRID: blockIdx.x = N-block(64), blockIdx.y = M-block(128), z = conv window.
//   MODE 0:+bias->f32  2:raw->f32(+z C offset)  3:fused score
//   MODE 4:+bias,relu->split planes  5:+bias->split planes
// Requires: M%128==0, K%64==0.
// ---------------------------------------------------------------------------
template<int MODE>
__global__ void __launch_bounds__(256, 2) tgemm(
    const h16* __restrict__ A, long long aPS, int lda, long long aZ,
    const h16* __restrict__ B, long long bPS, int ldb,
    const float* __restrict__ bias,
    float* __restrict__ C, int ldc, long long cZ,
    int Nn, int K, float oscale,
    const float* __restrict__ u, const float* __restrict__ sw,
    h16* __restrict__ Dh, long long dPS, int dldc, int wlim)
{
    extern __shared__ char smem[];
    const uint32_t sb = smem_u32(smem);
    const int tid  = threadIdx.x;
    const int lane = tid & 31, wid = tid >> 5;
    const int wm = wid >> 1, wn = wid & 1;            // 4 x 2 warp grid
    const int bn = blockIdx.x * 64, bm = blockIdx.y * 128;

    A += (long long)blockIdx.z * aZ;
    if (MODE == 2) C += (long long)blockIdx.z * cZ;

    float accM[2][4][4], accC[2][4][4];
#pragma unroll
    for (int i = 0; i < 2; i++)
#pragma unroll
        for (int j = 0; j < 4; j++)
#pragma unroll
            for (int r = 0; r < 4; r++) { accM[i][j][r] = 0.f; accC[i][j][r] = 0.f; }

    const uint32_t aOff = (uint32_t)((wm * 32 + (lane & 15)) * 144 + (lane >> 4) * 16);
    const uint32_t bOff = (uint32_t)((wn * 32 + (lane & 7) + ((lane >> 4) & 1) * 8) * 144
                                     + ((lane >> 3) & 1) * 16);

    const int nch = K >> 6;

    // loader: 3072 16B-vectors per stage (A: 2x128x8, B: 2x64x8), 12/thread
    auto load_chunk = [&](int s, int st) {
        const uint32_t base = sb + (uint32_t)st * STAGEB;
#pragma unroll
        for (int it = 0; it < 12; it++) {
            const int v = tid + it * 256;
            if (v < 2048) {                      // A planes (128 rows, 8 segs)
                const int plane = v >> 10;
                const int rem = v & 1023;
                const int row = rem >> 3, seg = rem & 7;
                const h16* g = A + (long long)plane * aPS +
                               (long long)(bm + row) * lda + s * 64 + seg * 8;
                cp16(base + plane * PLANEA + row * 144 + seg * 16, g, 16);
            } else {                             // B planes (64 rows, 8 segs)
                const int w = v - 2048;
                const int plane = w >> 9;
                const int rem = w & 511;
                const int row = rem >> 3, seg = rem & 7;
                const int n = bn + row;
                const bool ok = n < Nn;
                const h16* g = B + (long long)plane * bPS +
                               (long long)(ok ? n : 0) * ldb + s * 64 + seg * 8;
                cp16(base + 2 * PLANEA + plane * PLANEBB + row * 144 + seg * 16,
                     g, ok ? 16u : 0u);
            }
        }
        asm volatile("cp.async.commit_group;");
    };

    load_chunk(0, 0);
    for (int s = 0; s < nch; ++s) {
        // load(s) is the single pending group
        asm volatile("cp.async.wait_group 0;");
        // all threads: load(s) visible; compute(s-1) done -> buf (s+1)&1 free
        __syncthreads();
        if (s + 1 < nch) load_chunk(s + 1, (s + 1) & 1);

        const uint32_t stage = sb + (uint32_t)(s & 1) * STAGEB;
        const uint32_t bbase = stage + 2 * PLANEA;
#pragma unroll
        for (int kk = 0; kk < 4; kk++) {
            const uint32_t ko = kk * 32;          // 16 cols = 32 B
            uint32_t af[2][4], b0r[4][2], b1r[4][2];
#pragma unroll
            for (int i = 0; i < 2; i++)
                ldm4(af[i][0], af[i][1], af[i][2], af[i][3],
                     stage + aOff + ko + i * (16 * 144));
            ldm4(b0r[0][0], b0r[0][1], b0r[1][0], b0r[1][1], bbase + bOff + ko);
            ldm4(b0r[2][0], b0r[2][1], b0r[3][0], b0r[3][1],
                 bbase + bOff + ko + 16 * 144);
            ldm4(b1r[0][0], b1r[0][1], b1r[1][0], b1r[1][1],
                 bbase + PLANEBB + bOff + ko);
            ldm4(b1r[2][0], b1r[2][1], b1r[3][0], b1r[3][1],
                 bbase + PLANEBB + bOff + ko + 16 * 144);

#pragma unroll
            for (int i = 0; i < 2; i++)
#pragma unroll
                for (int j = 0; j < 4; j++) {
                    mma16816(accM[i][j], af[i], b0r[j]);
                    mma16816(accC[i][j], af[i], b1r[j]);
                }
#pragma unroll
            for (int i = 0; i < 2; i++)
                ldm4(af[i][0], af[i][1], af[i][2], af[i][3],
                     stage + PLANEA + aOff + ko + i * (16 * 144));
#pragma unroll
            for (int i = 0; i < 2; i++)
#pragma unroll
                for (int j = 0; j < 4; j++)
                    mma16816(accC[i][j], af[i], b0r[j]);
        }
    }

    // ---- epilogue ----
    const int gr = lane >> 2, tig = lane & 3;
    if (MODE == 3) {
#pragma unroll
        for (int i = 0; i < 2; i++) {
            const int m1 = bm + wm * 32 + i * 16 + gr;
            const int m2 = m1 + 8;
            const float* u1 = u + (long long)(m1 / NIMG) * DIM;
            const float* u2 = u + (long long)(m2 / NIMG) * DIM;
            float s1 = 0.f, s2 = 0.f;
#pragma unroll
            for (int j = 0; j < 4; j++) {
                const int c = bn + wn * 32 + j * 8 + 2 * tig;
                float w0 = sw[c], w1 = sw[c + 1];
                float v;
                v = (accM[i][j][0] + accC[i][j][0]) * oscale + u1[c];     s1 += fmaxf(v, 0.f) * w0;
                v = (accM[i][j][1] + accC[i][j][1]) * oscale + u1[c + 1]; s1 += fmaxf(v, 0.f) * w1;
                v = (accM[i][j][2] + accC[i][j][2]) * oscale + u2[c];     s2 += fmaxf(v, 0.f) * w0;
                v = (accM[i][j][3] + accC[i][j][3]) * oscale + u2[c + 1]; s2 += fmaxf(v, 0.f) * w1;
            }
            s1 += __shfl_xor_sync(0xffffffffu, s1, 1);
            s1 += __shfl_xor_sync(0xffffffffu, s1, 2);
            s2 += __shfl_xor_sync(0xffffffffu, s2, 1);
            s2 += __shfl_xor_sync(0xffffffffu, s2, 2);
            if (tig == 0) {
                atomicAdd(&g_score[m1], s1);
                atomicAdd(&g_score[m2], s2);
            }
        }
    } else if (MODE == 4 || MODE == 5) {
#pragma unroll
        for (int i = 0; i < 2; i++) {
            const int m1 = bm + wm * 32 + i * 16 + gr;
#pragma unroll
            for (int j = 0; j < 4; j++) {
                const int c = bn + wn * 32 + j * 8 + 2 * tig;
                if (c < wlim) {
                    float v0 = 0.f, v1 = 0.f, v2 = 0.f, v3 = 0.f;
                    if (c < Nn) {
                        const float b0 = bias[c], b1 = bias[c + 1];
                        v0 = (accM[i][j][0] + accC[i][j][0]) * oscale + b0;
                        v1 = (accM[i][j][1] + accC[i][j][1]) * oscale + b1;
                        v2 = (accM[i][j][2] + accC[i][j][2]) * oscale + b0;
                        v3 = (accM[i][j][3] + accC[i][j][3]) * oscale + b1;
                        if (MODE == 4) {
                            v0 = fmaxf(v0, 0.f); v1 = fmaxf(v1, 0.f);
                            v2 = fmaxf(v2, 0.f); v3 = fmaxf(v3, 0.f);
                        }
                    }
                    split_store(Dh, dPS, (long long)m1 * dldc + c, v0, v1);
                    split_store(Dh, dPS, (long long)(m1 + 8) * dldc + c, v2, v3);
                }
            }
        }
    } else {
#pragma unroll
        for (int i = 0; i < 2; i++) {
            const int m1 = bm + wm * 32 + i * 16 + gr;
#pragma unroll
            for (int j = 0; j < 4; j++) {
                const int c = bn + wn * 32 + j * 8 + 2 * tig;
                if (c < Nn) {
                    float b0 = 0.f, b1 = 0.f;
                    if (MODE != 2) { b0 = bias[c]; b1 = bias[c + 1]; }
                    float v0 = (accM[i][j][0] + accC[i][j][0]) * oscale + b0;
                    float v1 = (accM[i][j][1] + accC[i][j][1]) * oscale + b1;
                    float v2 = (accM[i][j][2] + accC[i][j][2]) * oscale + b0;
                    float v3 = (accM[i][j][3] + accC[i][j][3]) * oscale + b1;
                    *(float2*)&C[(long long)m1 * ldc + c]       = make_float2(v0, v1);
                    *(float2*)&C[(long long)(m1 + 8) * ldc + c] = make_float2(v2, v3);
                }
            }
        }
    }
}

// ---------------------------------------------------------------------------
__global__ void split2(const float* __restrict__ src, h16* __restrict__ dst,
                       long long ps, long long total, int srcCols, int dstCols,
                       float preScale)
{
    long long idx = (long long)blockIdx.x * blockDim.x + threadIdx.x;
    if (idx >= total) return;
    float x;
    if (srcCols == dstCols) x = src[idx];
    else {
        long long r = idx / dstCols;
        int k = (int)(idx - r * dstCols);
        x = (k < srcCols) ? src[r * srcCols + k] : 0.f;
    }
    x *= preScale;
    h16 h0 = __float2half_rn(x);
    h16 h1 = __float2half_rn(x - __half2float(h0));
    dst[idx] = h0; dst[ps + idx] = h1;
}

__global__ void split2T(const float* __restrict__ src, h16* __restrict__ dst,
                        long long ps, int N, int K, int Kpad, float preScale)
{
    int idx = blockIdx.x * blockDim.x + threadIdx.x;
    if (idx >= N * Kpad) return;
    int n = idx / Kpad, k = idx % Kpad;
    float x = (k < K) ? src[(long long)k * N + n] * preScale : 0.f;
    h16 h0 = __float2half_rn(x);
    h16 h1 = __float2half_rn(x - __half2float(h0));
    dst[idx] = h0; dst[ps + idx] = h1;
}

__global__ void conv_reduce_split(const float* __restrict__ bias, int T, int coff)
{
    int idx = blockIdx.x * blockDim.x + threadIdx.x;
    if (idx >= BATCH * 200) return;
    int c = idx % 200, n = idx / 200;
    float v = g_tmp[idx];
    for (int t = 1; t < T; t++) v = fmaxf(v, g_tmp[(size_t)t * TS + idx]);
    v = fmaxf(v + bias[c], 0.f);
    h16 h0 = __float2half_rn(v);
    h16 h1 = __float2half_rn(v - __half2float(h0));
    long long o = (long long)n * 640 + coff + c;
    g_ca[o] = h0; g_ca[CPS + o] = h1;
}

__global__ void zero_score()
{
    int i = blockIdx.x * blockDim.x + threadIdx.x;
    if (i < M5) g_score[i] = 0.f;
}

__global__ void finalize_f32(const float* __restrict__ fcs_b, float* __restrict__ out)
{
    int n = blockIdx.x * blockDim.x + threadIdx.x;
    if (n >= BATCH) return;
    float fb = fcs_b[0];
    float s[5];
#pragma unroll
    for (int i = 0; i < 5; i++) s[i] = g_score[n * 5 + i] + fb;
#pragma unroll
    for (int i = 0; i < 5; i++) {
        int si = n * 5 + i;
        out[si] = s[i];
        int r = 0;
#pragma unroll
        for (int j = 0; j < 5; j++)
            r += (s[j] > s[i]) || ((s[j] == s[i]) && (j < i));
        out[M5 + si] = (float)r;
    }
}

extern "C" void kernel_launch(void* const* d_in, const int* in_sizes, int n_in,
                              void* d_out, int out_size)
{
    const float* feats = (const float*)d_in[0];
    const float* w2    = (const float*)d_in[1];
    const float* b2    = (const float*)d_in[2];
    const float* w3    = (const float*)d_in[3];
    const float* b3    = (const float*)d_in[4];
    const float* w5    = (const float*)d_in[5];
    const float* b5    = (const float*)d_in[6];
    const float* fc1_w = (const float*)d_in[7];
    const float* fc1_b = (const float*)d_in[8];
    const float* fc2_w = (const float*)d_in[9];
    const float* fc2_b = (const float*)d_in[10];
    const float* fc0_w = (const float*)d_in[11];
    const float* fc0_b = (const float*)d_in[12];
    const float* fcs_w = (const float*)d_in[13];
    const float* fcs_b = (const float*)d_in[14];

    float *pt, *pu;
    cudaGetSymbolAddress((void**)&pt,  g_tmp);
    cudaGetSymbolAddress((void**)&pu,  g_u);
    h16 *fa, *ca, *ha, *cia, *w2a, *w3a, *w5a, *f1a, *f2a, *f0aa, *f0ua;
    cudaGetSymbolAddress((void**)&fa,   g_fa);
    cudaGetSymbolAddress((void**)&ca,   g_ca);
    cudaGetSymbolAddress((void**)&ha,   g_ha);
    cudaGetSymbolAddress((void**)&cia,  g_cia);
    cudaGetSymbolAddress((void**)&w2a,  g_w2a);
    cudaGetSymbolAddress((void**)&w3a,  g_w3a);
    cudaGetSymbolAddress((void**)&w5a,  g_w5a);
    cudaGetSymbolAddress((void**)&f1a,  g_f1a);
    cudaGetSymbolAddress((void**)&f2a,  g_f2a);
    cudaGetSymbolAddress((void**)&f0aa, g_f0aa);
    cudaGetSymbolAddress((void**)&f0ua, g_f0ua);

    cudaFuncSetAttribute(tgemm<0>, cudaFuncAttributeMaxDynamicSharedMemorySize, SMT);
    cudaFuncSetAttribute(tgemm<2>, cudaFuncAttributeMaxDynamicSharedMemorySize, SMT);
    cudaFuncSetAttribute(tgemm<3>, cudaFuncAttributeMaxDynamicSharedMemorySize, SMT);
    cudaFuncSetAttribute(tgemm<4>, cudaFuncAttributeMaxDynamicSharedMemorySize, SMT);
    cudaFuncSetAttribute(tgemm<5>, cudaFuncAttributeMaxDynamicSharedMemorySize, SMT);

    dim3 blk(256);
    const int MB = BATCH / 128;

    // ---- splits (feats + weights only) ----
    split2<<<(int)((83886080LL + 255) / 256), blk>>>(feats, fa, FPS, 83886080LL,
                                                     2560, 2560, 1.f);
    split2<<<(204800 + 255) / 256, blk>>>(w2, w2a, 200 * 1024, 204800, 1024, 1024, WSCALE);
    split2<<<(307200 + 255) / 256, blk>>>(w3, w3a, 200 * 1536, 307200, 1536, 1536, WSCALE);
    split2<<<(512000 + 255) / 256, blk>>>(w5, w5a, 200 * 2560, 512000, 2560, 2560, WSCALE);
    split2T<<<(600 * 640 + 255) / 256, blk>>>(fc1_w, f1a, 600 * 640, 600, 600, 640, WSCALE);
    split2T<<<(512 * 640 + 255) / 256, blk>>>(fc2_w, f2a, 512 * 640, 512, 600, 640, WSCALE);
    split2T<<<(512 * 512 + 255) / 256, blk>>>(fc0_w, f0aa, 512 * 512, 512, 512, 512, WSCALE);
    split2T<<<(512 * 512 + 255) / 256, blk>>>(fc0_w + (size_t)DIM * DIM, f0ua,
                                              512 * 512, 512, 512, 512, WSCALE);

    // ---- conv blocks (grid.x = N/64) ----
    tgemm<2><<<dim3(4, MB, 4), blk, SMT>>>(fa, FPS, 2560, 512,
        w2a, 200 * 1024, 1024, nullptr, pt, 200, TS, 200, 1024, IWSCALE,
        nullptr, nullptr, nullptr, 0, 0, 0);
    conv_reduce_split<<<(BATCH * 200 + 255) / 256, blk>>>(b2, 4, 0);

    tgemm<2><<<dim3(4, MB, 3), blk, SMT>>>(fa, FPS, 2560, 512,
        w3a, 200 * 1536, 1536, nullptr, pt, 200, TS, 200, 1536, IWSCALE,
        nullptr, nullptr, nullptr, 0, 0, 0);
    conv_reduce_split<<<(BATCH * 200 + 255) / 256, blk>>>(b3, 3, 200);

    // conv5: relu+bias -> split planes of g_ca at col offset 400
    tgemm<4><<<dim3(4, MB, 1), blk, SMT>>>(fa, FPS, 2560, 0,
        w5a, 200 * 2560, 2560, b5, nullptr, 0, 0, 200, 2560, IWSCALE,
        nullptr, nullptr, ca + 400, CPS, 640, 240);

    // fc1: relu+bias -> g_ha planes (cols 600..639 zero-filled)
    tgemm<4><<<dim3(10, MB, 1), blk, SMT>>>(ca, CPS, 640, 0,
        f1a, 600 * 640, 640, fc1_b, nullptr, 0, 0, 600, 640, IWSCALE,
        nullptr, nullptr, ha, CPS, 640, 640);

    // fc2: bias -> g_cia planes
    tgemm<5><<<dim3(8, MB, 1), blk, SMT>>>(ha, CPS, 640, 0,
        f2a, 512 * 640, 640, fc2_b, nullptr, 0, 0, 512, 640, IWSCALE,
        nullptr, nullptr, cia, CIPS, 512, 512);

    // u = ci @ fc0_w[512:] + fc0_b
    tgemm<0><<<dim3(8, MB, 1), blk, SMT>>>(cia, CIPS, 512, 0,
        f0ua, 512 * 512, 512, fc0_b, pu, DIM, 0, 512, 512, IWSCALE,
        nullptr, nullptr, nullptr, 0, 0, 0);

    // ---- fused score GEMM ----
    zero_score<<<(M5 + 255) / 256, blk>>>();
    tgemm<3><<<dim3(8, M5 / 128, 1), blk, SMT>>>(fa, FPS, 512, 0,
        f0aa, 512 * 512, 512, nullptr, nullptr, 0, 0, 512, 512, IWSCALE,
        pu, fcs_w, nullptr, 0, 0, 0);

    finalize_f32<<<(BATCH + 255) / 256, blk>>>(fcs_b, (float*)d_out);
}

// round 17
// speedup vs baseline: 2.4789x; 1.0041x over previous
#include <cuda_runtime.h>
#include <cuda_fp16.h>
#include <cstdint>

typedef __half h16;

#define BATCH 32768
#define NIMG  5
#define DIM   512
#define DCAT  600
#define M5    (BATCH * NIMG)
#define TS    (BATCH * 200)

#define WSCALE   128.0f
#define IWSCALE  (1.0f / 128.0f)

// ---- fp32 scratch ----
__device__ __align__(128) float g_tmp[4 * TS];
__device__ __align__(128) float g_u[BATCH * DIM];
__device__ __align__(128) float g_score[M5];

// ---- fp16 split planes (x = h0 + h1, ~24-bit total) ----
#define FPS  ((long long)BATCH * 2560)
#define CPS  ((long long)BATCH * 640)
#define CIPS ((long long)BATCH * 512)
__device__ __align__(128) h16 g_fa [2 * FPS];
__device__ __align__(128) h16 g_ca [2 * CPS];     // conv concat, 640-wide
__device__ __align__(128) h16 g_ha [2 * CPS];     // relu(fc1), 640-wide
__device__ __align__(128) h16 g_cia[2 * CIPS];    // fc2 out, 512-wide
__device__ __align__(128) h16 g_w2a[2 * 200 * 1024];
__device__ __align__(128) h16 g_w3a[2 * 200 * 1536];
__device__ __align__(128) h16 g_w5a[2 * 200 * 2560];
__device__ __align__(128) h16 g_f1a[2 * 600 * 640];
__device__ __align__(128) h16 g_f2a[2 * 512 * 640];
__device__ __align__(128) h16 g_f0aa[2 * 512 * 512];
__device__ __align__(128) h16 g_f0ua[2 * 512 * 512];

// ---- portable PTX helpers (sm_80+ ISA only) ----
__device__ __forceinline__ uint32_t smem_u32(const void* p) {
    uint32_t a;
    asm("{ .reg .u64 t; cvta.to.shared.u64 t, %1; cvt.u32.u64 %0, t; }"
        : "=r"(a) : "l"(p));
    return a;
}
__device__ __forceinline__ void cp16(uint32_t saddr, const void* gaddr, uint32_t srcsz) {
    asm volatile("cp.async.cg.shared.global [%0], [%1], 16, %2;"
                 :: "r"(saddr), "l"(gaddr), "r"(srcsz));
}
__device__ __forceinline__ void ldm4(uint32_t& r0, uint32_t& r1, uint32_t& r2,
                                     uint32_t& r3, uint32_t addr) {
    asm volatile("ldmatrix.sync.aligned.m8n8.x4.shared.b16 {%0,%1,%2,%3}, [%4];"
                 : "=r"(r0), "=r"(r1), "=r"(r2), "=r"(r3) : "r"(addr));
}
__device__ __forceinline__ void mma16816(float* d, const uint32_t* a,
                                         const uint32_t* b) {
    asm volatile(
        "mma.sync.aligned.m16n8k16.row.col.f32.f16.f16.f32 "
        "{%0,%1,%2,%3}, {%4,%5,%6,%7}, {%8,%9}, {%0,%1,%2,%3};"
        : "+f"(d[0]), "+f"(d[1]), "+f"(d[2]), "+f"(d[3])
        : "r"(a[0]), "r"(a[1]), "r"(a[2]), "r"(a[3]), "r"(b[0]), "r"(b[1]));
}
__device__ __forceinline__ void split_store(h16* dst, long long dPS,
                                            long long idx, float v0, float v1) {
    h16 a0 = __float2half_rn(v0);
    h16 b0 = __float2half_rn(v1);
    h16 a1 = __float2half_rn(v0 - __half2float(a0));
    h16 b1 = __float2half_rn(v1 - __half2float(b0));
    *(__half2*)&dst[idx]       = __halves2half2(a0, b0);
    *(__half2*)&dst[dPS + idx] = __halves2half2(a1, b1);
}

// smem: 2-stage ring; per stage 2 A planes (128 rows) + 2 B planes (64 rows),
// k64 chunks: rows 128B data padded to 144B (conflict-free ldmatrix).
#define PLANEA 18432           // 128 * 144
#define PLANEBB 9216           // 64 * 144
#define STAGEB (2 * PLANEA + 2 * PLANEBB)   // 55296
#define SMT    (2 * STAGEB)                  // 110592 B -> 2 CTAs/SM

// ---------------------------------------------------------------------------
// Tensor-core GEMM, fp16x2 split, dual accumulators. Block tile 128x64,
// 8 warps in 4x2, warp tile 32x32, K chunks of 64, double-buffered.
//   GRID: blockIdx.x = window*NBx + N-block  (windows schedule-adjacent ->
//         overlapping conv A strips stay L2-resident), blockIdx.y = M-block.
//   MODE 0:+bias->f32  2:raw->f32(+window C offset)  3:fused score
//   MODE 4:+bias,relu->split planes  5:+bias->split planes
// Requires: M%128==0, K%64==0.
// ---------------------------------------------------------------------------
template<int MODE>
__global__ void __launch_bounds__(256, 2) tgemm(
    const h16* __restrict__ A, long long aPS, int lda, long long aZ,
    const h16* __restrict__ B, long long bPS, int ldb,
    const float* __restrict__ bias,
    float* __restrict__ C, int ldc, long long cZ,
    int Nn, int K, float oscale, int NBx,
    const float* __restrict__ u, const float* __restrict__ sw,
    h16* __restrict__ Dh, long long dPS, int dldc, int wlim)
{
    extern __shared__ char smem[];
    const uint32_t sb = smem_u32(smem);
    const int tid  = threadIdx.x;
    const int lane = tid & 31, wid = tid >> 5;
    const int wm = wid >> 1, wn = wid & 1;            // 4 x 2 warp grid
    const int xw = blockIdx.x / NBx;                  // conv window
    const int bn = (blockIdx.x - xw * NBx) * 64;
    const int bm = blockIdx.y * 128;

    A += (long long)xw * aZ;
    if (MODE == 2) C += (long long)xw * cZ;

    float accM[2][4][4], accC[2][4][4];
#pragma unroll
    for (int i = 0; i < 2; i++)
#pragma unroll
        for (int j = 0; j < 4; j++)
#pragma unroll
            for (int r = 0; r < 4; r++) { accM[i][j][r] = 0.f; accC[i][j][r] = 0.f; }

    const uint32_t aOff = (uint32_t)((wm * 32 + (lane & 15)) * 144 + (lane >> 4) * 16);
    const uint32_t bOff = (uint32_t)((wn * 32 + (lane & 7) + ((lane >> 4) & 1) * 8) * 144
                                     + ((lane >> 3) & 1) * 16);

    const int nch = K >> 6;

    // loader: 3072 16B-vectors per stage (A: 2x128x8, B: 2x64x8), 12/thread
    auto load_chunk = [&](int s, int st) {
        const uint32_t base = sb + (uint32_t)st * STAGEB;
#pragma unroll
        for (int it = 0; it < 12; it++) {
            const int v = tid + it * 256;
            if (v < 2048) {                      // A planes (128 rows, 8 segs)
                const int plane = v >> 10;
                const int rem = v & 1023;
                const int row = rem >> 3, seg = rem & 7;
                const h16* g = A + (long long)plane * aPS +
                               (long long)(bm + row) * lda + s * 64 + seg * 8;
                cp16(base + plane * PLANEA + row * 144 + seg * 16, g, 16);
            } else {                             // B planes (64 rows, 8 segs)
                const int w = v - 2048;
                const int plane = w >> 9;
                const int rem = w & 511;
                const int row = rem >> 3, seg = rem & 7;
                const int n = bn + row;
                const bool ok = n < Nn;
                const h16* g = B + (long long)plane * bPS +
                               (long long)(ok ? n : 0) * ldb + s * 64 + seg * 8;
                cp16(base + 2 * PLANEA + plane * PLANEBB + row * 144 + seg * 16,
                     g, ok ? 16u : 0u);
            }
        }
        asm volatile("cp.async.commit_group;");
    };

    load_chunk(0, 0);
    for (int s = 0; s < nch; ++s) {
        asm volatile("cp.async.wait_group 0;");
        __syncthreads();
        if (s + 1 < nch) load_chunk(s + 1, (s + 1) & 1);

        const uint32_t stage = sb + (uint32_t)(s & 1) * STAGEB;
        const uint32_t bbase = stage + 2 * PLANEA;
#pragma unroll
        for (int kk = 0; kk < 4; kk++) {
            const uint32_t ko = kk * 32;          // 16 cols = 32 B
            uint32_t a0f[2][4], a1f[2][4], b0r[4][2], b1r[4][2];
            // preload ALL fragments for this k16 step (no mid-stream ldm4)
#pragma unroll
            for (int i = 0; i < 2; i++) {
                ldm4(a0f[i][0], a0f[i][1], a0f[i][2], a0f[i][3],
                     stage + aOff + ko + i * (16 * 144));
                ldm4(a1f[i][0], a1f[i][1], a1f[i][2], a1f[i][3],
                     stage + PLANEA + aOff + ko + i * (16 * 144));
            }
            ldm4(b0r[0][0], b0r[0][1], b0r[1][0], b0r[1][1], bbase + bOff + ko);
            ldm4(b0r[2][0], b0r[2][1], b0r[3][0], b0r[3][1],
                 bbase + bOff + ko + 16 * 144);
            ldm4(b1r[0][0], b1r[0][1], b1r[1][0], b1r[1][1],
                 bbase + PLANEBB + bOff + ko);
            ldm4(b1r[2][0], b1r[2][1], b1r[3][0], b1r[3][1],
                 bbase + PLANEBB + bOff + ko + 16 * 144);

            // 48 MMAs, uninterrupted
#pragma unroll
            for (int i = 0; i < 2; i++)
#pragma unroll
                for (int j = 0; j < 4; j++) {
                    mma16816(accM[i][j], a0f[i], b0r[j]);
                    mma16816(accC[i][j], a0f[i], b1r[j]);
                    mma16816(accC[i][j], a1f[i], b0r[j]);
                }
        }
    }

    // ---- epilogue ----
    const int gr = lane >> 2, tig = lane & 3;
    if (MODE == 3) {
#pragma unroll
        for (int i = 0; i < 2; i++) {
            const int m1 = bm + wm * 32 + i * 16 + gr;
            const int m2 = m1 + 8;
            const float* u1 = u + (long long)(m1 / NIMG) * DIM;
            const float* u2 = u + (long long)(m2 / NIMG) * DIM;
            float s1 = 0.f, s2 = 0.f;
#pragma unroll
            for (int j = 0; j < 4; j++) {
                const int c = bn + wn * 32 + j * 8 + 2 * tig;
                float w0 = sw[c], w1 = sw[c + 1];
                float v;
                v = (accM[i][j][0] + accC[i][j][0]) * oscale + u1[c];     s1 += fmaxf(v, 0.f) * w0;
                v = (accM[i][j][1] + accC[i][j][1]) * oscale + u1[c + 1]; s1 += fmaxf(v, 0.f) * w1;
                v = (accM[i][j][2] + accC[i][j][2]) * oscale + u2[c];     s2 += fmaxf(v, 0.f) * w0;
                v = (accM[i][j][3] + accC[i][j][3]) * oscale + u2[c + 1]; s2 += fmaxf(v, 0.f) * w1;
            }
            s1 += __shfl_xor_sync(0xffffffffu, s1, 1);
            s1 += __shfl_xor_sync(0xffffffffu, s1, 2);
            s2 += __shfl_xor_sync(0xffffffffu, s2, 1);
            s2 += __shfl_xor_sync(0xffffffffu, s2, 2);
            if (tig == 0) {
                atomicAdd(&g_score[m1], s1);
                atomicAdd(&g_score[m2], s2);
            }
        }
    } else if (MODE == 4 || MODE == 5) {
#pragma unroll
        for (int i = 0; i < 2; i++) {
            const int m1 = bm + wm * 32 + i * 16 + gr;
#pragma unroll
            for (int j = 0; j < 4; j++) {
                const int c = bn + wn * 32 + j * 8 + 2 * tig;
                if (c < wlim) {
                    float v0 = 0.f, v1 = 0.f, v2 = 0.f, v3 = 0.f;
                    if (c < Nn) {
                        const float b0 = bias[c], b1 = bias[c + 1];
                        v0 = (accM[i][j][0] + accC[i][j][0]) * oscale + b0;
                        v1 = (accM[i][j][1] + accC[i][j][1]) * oscale + b1;
                        v2 = (accM[i][j][2] + accC[i][j][2]) * oscale + b0;
                        v3 = (accM[i][j][3] + accC[i][j][3]) * oscale + b1;
                        if (MODE == 4) {
                            v0 = fmaxf(v0, 0.f); v1 = fmaxf(v1, 0.f);
                            v2 = fmaxf(v2, 0.f); v3 = fmaxf(v3, 0.f);
                        }
                    }
                    split_store(Dh, dPS, (long long)m1 * dldc + c, v0, v1);
                    split_store(Dh, dPS, (long long)(m1 + 8) * dldc + c, v2, v3);
                }
            }
        }
    } else {
#pragma unroll
        for (int i = 0; i < 2; i++) {
            const int m1 = bm + wm * 32 + i * 16 + gr;
#pragma unroll
            for (int j = 0; j < 4; j++) {
                const int c = bn + wn * 32 + j * 8 + 2 * tig;
                if (c < Nn) {
                    float b0 = 0.f, b1 = 0.f;
                    if (MODE != 2) { b0 = bias[c]; b1 = bias[c + 1]; }
                    float v0 = (accM[i][j][0] + accC[i][j][0]) * oscale + b0;
                    float v1 = (accM[i][j][1] + accC[i][j][1]) * oscale + b1;
                    float v2 = (accM[i][j][2] + accC[i][j][2]) * oscale + b0;
                    float v3 = (accM[i][j][3] + accC[i][j][3]) * oscale + b1;
                    *(float2*)&C[(long long)m1 * ldc + c]       = make_float2(v0, v1);
                    *(float2*)&C[(long long)(m1 + 8) * ldc + c] = make_float2(v2, v3);
                }
            }
        }
    }
}

// ---------------------------------------------------------------------------
__global__ void split2(const float* __restrict__ src, h16* __restrict__ dst,
                       long long ps, long long total, int srcCols, int dstCols,
                       float preScale)
{
    long long idx = (long long)blockIdx.x * blockDim.x + threadIdx.x;
    if (idx >= total) return;
    float x;
    if (srcCols == dstCols) x = src[idx];
    else {
        long long r = idx / dstCols;
        int k = (int)(idx - r * dstCols);
        x = (k < srcCols) ? src[r * srcCols + k] : 0.f;
    }
    x *= preScale;
    h16 h0 = __float2half_rn(x);
    h16 h1 = __float2half_rn(x - __half2float(h0));
    dst[idx] = h0; dst[ps + idx] = h1;
}

__global__ void split2T(const float* __restrict__ src, h16* __restrict__ dst,
                        long long ps, int N, int K, int Kpad, float preScale)
{
    int idx = blockIdx.x * blockDim.x + threadIdx.x;
    if (idx >= N * Kpad) return;
    int n = idx / Kpad, k = idx % Kpad;
    float x = (k < K) ? src[(long long)k * N + n] * preScale : 0.f;
    h16 h0 = __float2half_rn(x);
    h16 h1 = __float2half_rn(x - __half2float(h0));
    dst[idx] = h0; dst[ps + idx] = h1;
}

__global__ void conv_reduce_split(const float* __restrict__ bias, int T, int coff)
{
    int idx = blockIdx.x * blockDim.x + threadIdx.x;
    if (idx >= BATCH * 200) return;
    int c = idx % 200, n = idx / 200;
    float v = g_tmp[idx];
    for (int t = 1; t < T; t++) v = fmaxf(v, g_tmp[(size_t)t * TS + idx]);
    v = fmaxf(v + bias[c], 0.f);
    h16 h0 = __float2half_rn(v);
    h16 h1 = __float2half_rn(v - __half2float(h0));
    long long o = (long long)n * 640 + coff + c;
    g_ca[o] = h0; g_ca[CPS + o] = h1;
}

__global__ void zero_score()
{
    int i = blockIdx.x * blockDim.x + threadIdx.x;
    if (i < M5) g_score[i] = 0.f;
}

__global__ void finalize_f32(const float* __restrict__ fcs_b, float* __restrict__ out)
{
    int n = blockIdx.x * blockDim.x + threadIdx.x;
    if (n >= BATCH) return;
    float fb = fcs_b[0];
    float s[5];
#pragma unroll
    for (int i = 0; i < 5; i++) s[i] = g_score[n * 5 + i] + fb;
#pragma unroll
    for (int i = 0; i < 5; i++) {
        int si = n * 5 + i;
        out[si] = s[i];
        int r = 0;
#pragma unroll
        for (int j = 0; j < 5; j++)
            r += (s[j] > s[i]) || ((s[j] == s[i]) && (j < i));
        out[M5 + si] = (float)r;
    }
}

extern "C" void kernel_launch(void* const* d_in, const int* in_sizes, int n_in,
                              void* d_out, int out_size)
{
    const float* feats = (const float*)d_in[0];
    const float* w2    = (const float*)d_in[1];
    const float* b2    = (const float*)d_in[2];
    const float* w3    = (const float*)d_in[3];
    const float* b3    = (const float*)d_in[4];
    const float* w5    = (const float*)d_in[5];
    const float* b5    = (const float*)d_in[6];
    const float* fc1_w = (const float*)d_in[7];
    const float* fc1_b = (const float*)d_in[8];
    const float* fc2_w = (const float*)d_in[9];
    const float* fc2_b = (const float*)d_in[10];
    const float* fc0_w = (const float*)d_in[11];
    const float* fc0_b = (const float*)d_in[12];
    const float* fcs_w = (const float*)d_in[13];
    const float* fcs_b = (const float*)d_in[14];

    float *pt, *pu;
    cudaGetSymbolAddress((void**)&pt,  g_tmp);
    cudaGetSymbolAddress((void**)&pu,  g_u);
    h16 *fa, *ca, *ha, *cia, *w2a, *w3a, *w5a, *f1a, *f2a, *f0aa, *f0ua;
    cudaGetSymbolAddress((void**)&fa,   g_fa);
    cudaGetSymbolAddress((void**)&ca,   g_ca);
    cudaGetSymbolAddress((void**)&ha,   g_ha);
    cudaGetSymbolAddress((void**)&cia,  g_cia);
    cudaGetSymbolAddress((void**)&w2a,  g_w2a);
    cudaGetSymbolAddress((void**)&w3a,  g_w3a);
    cudaGetSymbolAddress((void**)&w5a,  g_w5a);
    cudaGetSymbolAddress((void**)&f1a,  g_f1a);
    cudaGetSymbolAddress((void**)&f2a,  g_f2a);
    cudaGetSymbolAddress((void**)&f0aa, g_f0aa);
    cudaGetSymbolAddress((void**)&f0ua, g_f0ua);

    cudaFuncSetAttribute(tgemm<0>, cudaFuncAttributeMaxDynamicSharedMemorySize, SMT);
    cudaFuncSetAttribute(tgemm<2>, cudaFuncAttributeMaxDynamicSharedMemorySize, SMT);
    cudaFuncSetAttribute(tgemm<3>, cudaFuncAttributeMaxDynamicSharedMemorySize, SMT);
    cudaFuncSetAttribute(tgemm<4>, cudaFuncAttributeMaxDynamicSharedMemorySize, SMT);
    cudaFuncSetAttribute(tgemm<5>, cudaFuncAttributeMaxDynamicSharedMemorySize, SMT);

    dim3 blk(256);
    const int MB = BATCH / 128;

    // ---- splits (feats + weights only) ----
    split2<<<(int)((83886080LL + 255) / 256), blk>>>(feats, fa, FPS, 83886080LL,
                                                     2560, 2560, 1.f);
    split2<<<(204800 + 255) / 256, blk>>>(w2, w2a, 200 * 1024, 204800, 1024, 1024, WSCALE);
    split2<<<(307200 + 255) / 256, blk>>>(w3, w3a, 200 * 1536, 307200, 1536, 1536, WSCALE);
    split2<<<(512000 + 255) / 256, blk>>>(w5, w5a, 200 * 2560, 512000, 2560, 2560, WSCALE);
    split2T<<<(600 * 640 + 255) / 256, blk>>>(fc1_w, f1a, 600 * 640, 600, 600, 640, WSCALE);
    split2T<<<(512 * 640 + 255) / 256, blk>>>(fc2_w, f2a, 512 * 640, 512, 600, 640, WSCALE);
    split2T<<<(512 * 512 + 255) / 256, blk>>>(fc0_w, f0aa, 512 * 512, 512, 512, 512, WSCALE);
    split2T<<<(512 * 512 + 255) / 256, blk>>>(fc0_w + (size_t)DIM * DIM, f0ua,
                                              512 * 512, 512, 512, 512, WSCALE);

    // ---- conv blocks (windows folded into grid.x: x = window*4 + nblock) ----
    tgemm<2><<<dim3(4 * 4, MB, 1), blk, SMT>>>(fa, FPS, 2560, 512,
        w2a, 200 * 1024, 1024, nullptr, pt, 200, TS, 200, 1024, IWSCALE, 4,
        nullptr, nullptr, nullptr, 0, 0, 0);
    conv_reduce_split<<<(BATCH * 200 + 255) / 256, blk>>>(b2, 4, 0);

    tgemm<2><<<dim3(4 * 3, MB, 1), blk, SMT>>>(fa, FPS, 2560, 512,
        w3a, 200 * 1536, 1536, nullptr, pt, 200, TS, 200, 1536, IWSCALE, 4,
        nullptr, nullptr, nullptr, 0, 0, 0);
    conv_reduce_split<<<(BATCH * 200 + 255) / 256, blk>>>(b3, 3, 200);

    // conv5: relu+bias -> split planes of g_ca at col offset 400
    tgemm<4><<<dim3(4, MB, 1), blk, SMT>>>(fa, FPS, 2560, 0,
        w5a, 200 * 2560, 2560, b5, nullptr, 0, 0, 200, 2560, IWSCALE, 4,
        nullptr, nullptr, ca + 400, CPS, 640, 240);

    // fc1: relu+bias -> g_ha planes (cols 600..639 zero-filled)
    tgemm<4><<<dim3(10, MB, 1), blk, SMT>>>(ca, CPS, 640, 0,
        f1a, 600 * 640, 640, fc1_b, nullptr, 0, 0, 600, 640, IWSCALE, 10,
        nullptr, nullptr, ha, CPS, 640, 640);

    // fc2: bias -> g_cia planes
    tgemm<5><<<dim3(8, MB, 1), blk, SMT>>>(ha, CPS, 640, 0,
        f2a, 512 * 640, 640, fc2_b, nullptr, 0, 0, 512, 640, IWSCALE, 8,
        nullptr, nullptr, cia, CIPS, 512, 512);

    // u = ci @ fc0_w[512:] + fc0_b
    tgemm<0><<<dim3(8, MB, 1), blk, SMT>>>(cia, CIPS, 512, 0,
        f0ua, 512 * 512, 512, fc0_b, pu, DIM, 0, 512, 512, IWSCALE, 8,
        nullptr, nullptr, nullptr, 0, 0, 0);

    // ---- fused score GEMM ----
    zero_score<<<(M5 + 255) / 256, blk>>>();
    tgemm<3><<<dim3(8, M5 / 128, 1), blk, SMT>>>(fa, FPS, 512, 0,
        f0aa, 512 * 512, 512, nullptr, nullptr, 0, 0, 512, 512, IWSCALE, 8,
        pu, fcs_w, nullptr, 0, 0, 0);

    finalize_f32<<<(BATCH + 255) / 256, blk>>>(fcs_b, (float*)d_out);
}